// round 5
// baseline (speedup 1.0000x reference)
#include <cuda_runtime.h>
#include <math.h>
#include <stdint.h>

// Problem dims (fixed by the dataset)
#define BATCH 4
#define SEQ   4096
#define DIM   1024
#define NTOK  (BATCH * SEQ)   // 16384

#define BM 256                 // CTA tile M
#define BN 128                 // CTA tile N
#define KC 32                  // K chunk per smem stage
#define PAD 36                 // row stride in floats (32 + 4 pad)
#define NSTAGE 3

// flags
#define F_CAUSAL 1   // Kend = min(Kfull, (bm+1)*BM)
#define F_TRI    2   // skip tiles entirely above the diagonal
#define F_ROUND  4   // round epilogue output to tf32 (rna)

// Scratch in device globals (no cudaMalloc allowed)
__device__ float g_q[(size_t)NTOK * DIM];
__device__ float g_k[(size_t)NTOK * DIM];
__device__ float g_v[(size_t)NTOK * DIM];
__device__ float g_ctx[(size_t)NTOK * DIM];   // holds rounded x first, then ctx
__device__ float g_p[(size_t)BATCH * SEQ * SEQ];
__device__ float g_wt[(size_t)4 * DIM * DIM];     // Wq^T, Wk^T, Wv^T, Wo^T (tf32-rounded)
__device__ float g_vt[(size_t)BATCH * DIM * SEQ]; // V^T per batch (tf32-rounded)

// ---------------------------------------------------------------------------
// helpers
// ---------------------------------------------------------------------------
__device__ __forceinline__ uint32_t smem_u32(const void* p) {
    uint32_t a;
    asm("{ .reg .u64 t; cvta.to.shared.u64 t, %1; cvt.u32.u64 %0, t; }"
        : "=r"(a) : "l"(p));
    return a;
}

__device__ __forceinline__ float rna_tf32(float x) {
    uint32_t r;
    asm("cvt.rna.tf32.f32 %0, %1;" : "=r"(r) : "f"(x));
    return __uint_as_float(r);
}

__device__ __forceinline__ void cp16(uint32_t saddr, const void* gaddr) {
    asm volatile("cp.async.cg.shared.global [%0], [%1], 16;"
                 :: "r"(saddr), "l"(gaddr));
}
#define CP_COMMIT() asm volatile("cp.async.commit_group;" ::: "memory")
#define CP_WAIT(n)  asm volatile("cp.async.wait_group %0;" :: "n"(n) : "memory")

__device__ __forceinline__ void mma_tf32(float* c, const uint32_t* a, const uint32_t* b) {
    asm volatile(
        "mma.sync.aligned.m16n8k8.row.col.f32.tf32.tf32.f32 "
        "{%0,%1,%2,%3}, {%4,%5,%6,%7}, {%8,%9}, {%0,%1,%2,%3};"
        : "+f"(c[0]), "+f"(c[1]), "+f"(c[2]), "+f"(c[3])
        : "r"(a[0]), "r"(a[1]), "r"(a[2]), "r"(a[3]), "r"(b[0]), "r"(b[1]));
}

// Smem: NSTAGE stages, each = A[BM][PAD] + B[BN][PAD] floats
#define A_FLOATS     (BM * PAD)                   // 9216
#define B_FLOATS     (BN * PAD)                   // 4608
#define STAGE_FLOATS (A_FLOATS + B_FLOATS)        // 13824
#define STAGE_BYTES  (STAGE_FLOATS * 4)           // 55296
#define A_BYTES      (A_FLOATS * 4)               // 36864
#define SMEM_SZ      (NSTAGE * STAGE_BYTES)       // 165888

// ---------------------------------------------------------------------------
// tf32 tensor-core GEMM: C[m,n] = scale * sum_k A[m,k] * Bt[n,k] (+ bias[n])
// A row-major [M x Kfull] (lda), Bt row-major [N x Kfull] (ldb; = B col-major).
// CTA 256x128, 8 warps (4x2), warp tile 64x64, mma m16n8k8, 3-stage cp.async.
// Operands must already be tf32-valued fp32 (pre-rounded) for full precision.
// ---------------------------------------------------------------------------
__global__ __launch_bounds__(256, 1) void mma_gemm(
    const float* __restrict__ A, const float* __restrict__ Bt,
    const float* __restrict__ bias, float* __restrict__ C,
    int lda, int ldb, int ldc, int Kfull, int flags, float scale,
    size_t sA, size_t sB, size_t sC)
{
    const int bm = blockIdx.y, bn = blockIdx.x, bz = blockIdx.z;
    if ((flags & F_TRI) && bn >= 2 * (bm + 1)) return;   // tile entirely above diag

    extern __shared__ __align__(16) float smem[];
    const uint32_t sbase = smem_u32(smem);

    const int tid  = threadIdx.x;
    const int wid  = tid >> 5, lane = tid & 31;
    const int wm   = (wid & 3) * 64;       // warp row offset in tile
    const int wn   = (wid >> 2) * 64;      // warp col offset in tile
    const int gid  = lane >> 2, tig = lane & 3;

    int Kend = Kfull;
    if (flags & F_CAUSAL) { int lim = (bm + 1) * BM; if (lim < Kend) Kend = lim; }
    const int NK = Kend / KC;

    const float* Ab = A + sA * bz + (size_t)(bm * BM) * lda;
    const float* Bb = Bt + sB * bz + (size_t)(bn * BN) * ldb;

    // gmem->smem mapping: row = tid/8 (+32 per step), col = (tid%8)*4 fixed
    const int lr = tid >> 3;
    const int lc = (tid & 7) << 2;

    auto issue = [&](int kc, int s) {
        const int k0 = kc * KC;
        const uint32_t base = sbase + s * STAGE_BYTES;
#pragma unroll
        for (int t = 0; t < 8; t++) {
            const int r = lr + t * 32;
            cp16(base + (uint32_t)(r * PAD + lc) * 4,
                 Ab + (size_t)r * lda + k0 + lc);
        }
#pragma unroll
        for (int t = 0; t < 4; t++) {
            const int r = lr + t * 32;
            cp16(base + A_BYTES + (uint32_t)(r * PAD + lc) * 4,
                 Bb + (size_t)r * ldb + k0 + lc);
        }
        CP_COMMIT();
    };

    float acc[4][8][4];
#pragma unroll
    for (int mt = 0; mt < 4; mt++)
#pragma unroll
        for (int nt = 0; nt < 8; nt++)
#pragma unroll
            for (int j = 0; j < 4; j++) acc[mt][nt][j] = 0.f;

    issue(0, 0);
    if (NK > 1) issue(1, 1);

    for (int kc = 0; kc < NK; kc++) {
        if (kc + 1 < NK) { CP_WAIT(1); } else { CP_WAIT(0); }
        __syncthreads();
        if (kc + 2 < NK) issue(kc + 2, (kc + 2) % NSTAGE);

        const float* As = smem + (kc % NSTAGE) * STAGE_FLOATS;
        const float* Bs = As + A_FLOATS;

#pragma unroll
        for (int ks = 0; ks < 4; ks++) {
            const int kb = ks * 8 + tig;
            uint32_t a[4][4], b[8][2];
#pragma unroll
            for (int mt = 0; mt < 4; mt++) {
                const int r = wm + mt * 16 + gid;
                a[mt][0] = __float_as_uint(As[r * PAD + kb]);
                a[mt][1] = __float_as_uint(As[(r + 8) * PAD + kb]);
                a[mt][2] = __float_as_uint(As[r * PAD + kb + 4]);
                a[mt][3] = __float_as_uint(As[(r + 8) * PAD + kb + 4]);
            }
#pragma unroll
            for (int nt = 0; nt < 8; nt++) {
                const int col = wn + nt * 8 + gid;
                b[nt][0] = __float_as_uint(Bs[col * PAD + kb]);
                b[nt][1] = __float_as_uint(Bs[col * PAD + kb + 4]);
            }
#pragma unroll
            for (int mt = 0; mt < 4; mt++)
#pragma unroll
                for (int nt = 0; nt < 8; nt++)
                    mma_tf32(acc[mt][nt], a[mt], b[nt]);
        }
        __syncthreads();
    }

    // Epilogue
    const int do_round = flags & F_ROUND;
    float* Cb = C + sC * bz;
#pragma unroll
    for (int mt = 0; mt < 4; mt++) {
        const int row0 = bm * BM + wm + mt * 16 + gid;
#pragma unroll
        for (int nt = 0; nt < 8; nt++) {
            const int col = bn * BN + wn + nt * 8 + tig * 2;
            float b0 = 0.f, b1 = 0.f;
            if (bias) { b0 = bias[col]; b1 = bias[col + 1]; }
            float2 v0, v1;
            v0.x = acc[mt][nt][0] * scale + b0;
            v0.y = acc[mt][nt][1] * scale + b1;
            v1.x = acc[mt][nt][2] * scale + b0;
            v1.y = acc[mt][nt][3] * scale + b1;
            if (do_round) {
                v0.x = rna_tf32(v0.x); v0.y = rna_tf32(v0.y);
                v1.x = rna_tf32(v1.x); v1.y = rna_tf32(v1.y);
            }
            *(float2*)(Cb + (size_t)row0 * ldc + col) = v0;
            *(float2*)(Cb + (size_t)(row0 + 8) * ldc + col) = v1;
        }
    }
}

// ---------------------------------------------------------------------------
// Tiled transpose with tf32 rounding: out[c, r] = rna(in[r, c]).
// ---------------------------------------------------------------------------
__global__ __launch_bounds__(256) void transpose_k(
    const float* __restrict__ in, float* __restrict__ out,
    int rows, int cols, size_t sIn, size_t sOut)
{
    __shared__ float tile[32][33];
    const int bx = blockIdx.x * 32, by = blockIdx.y * 32, bz = blockIdx.z;
    const float* ip = in + sIn * bz;
    float* op = out + sOut * bz;
    const int tx = threadIdx.x, ty = threadIdx.y;
#pragma unroll
    for (int i = 0; i < 4; i++)
        tile[ty + i * 8][tx] = ip[(size_t)(by + ty + i * 8) * cols + bx + tx];
    __syncthreads();
#pragma unroll
    for (int i = 0; i < 4; i++)
        op[(size_t)(bx + ty + i * 8) * rows + by + tx] = rna_tf32(tile[tx][ty + i * 8]);
}

// ---------------------------------------------------------------------------
// Elementwise tf32 rounding pass (for x).
// ---------------------------------------------------------------------------
__global__ __launch_bounds__(256) void round_pass(
    const float* __restrict__ in, float* __restrict__ out)
{
    const size_t i = ((size_t)blockIdx.x * 256 + threadIdx.x) * 4;
    float4 v = *(const float4*)(in + i);
    v.x = rna_tf32(v.x); v.y = rna_tf32(v.y);
    v.z = rna_tf32(v.z); v.w = rna_tf32(v.w);
    *(float4*)(out + i) = v;
}

// ---------------------------------------------------------------------------
// Causal row softmax; writes vals for j<n, zeros for n<=j<limit where
// limit = 256-aligned causal boundary (PV never reads beyond it). tf32-rounded.
// ---------------------------------------------------------------------------
__global__ __launch_bounds__(256) void softmax_causal(float* __restrict__ P)
{
    __shared__ float red[33];
    const int row = blockIdx.x;
    const int bz  = blockIdx.y;
    float* p = P + ((size_t)bz * SEQ + row) * SEQ;
    const int n = row + 1;
    const int limit = ((row >> 8) + 1) << 8;   // (row/BM + 1) * BM
    const int t = threadIdx.x;

    float vals[16];
    float mx = -INFINITY;
#pragma unroll
    for (int i = 0; i < 16; i++) {
        int j = t + (i << 8);
        float v = (j < n) ? p[j] : -INFINITY;
        vals[i] = v;
        mx = fmaxf(mx, v);
    }
#pragma unroll
    for (int o = 16; o; o >>= 1) mx = fmaxf(mx, __shfl_xor_sync(0xffffffffu, mx, o));
    if ((t & 31) == 0) red[t >> 5] = mx;
    __syncthreads();
    if (t < 32) {
        float v = (t < 8) ? red[t] : -INFINITY;
#pragma unroll
        for (int o = 4; o; o >>= 1) v = fmaxf(v, __shfl_xor_sync(0xffffffffu, v, o));
        if (t == 0) red[32] = v;
    }
    __syncthreads();
    mx = red[32];

    float sum = 0.f;
#pragma unroll
    for (int i = 0; i < 16; i++) {
        int j = t + (i << 8);
        float v = (j < n) ? expf(vals[i] - mx) : 0.f;
        vals[i] = v;
        sum += v;
    }
#pragma unroll
    for (int o = 16; o; o >>= 1) sum += __shfl_xor_sync(0xffffffffu, sum, o);
    __syncthreads();
    if ((t & 31) == 0) red[t >> 5] = sum;
    __syncthreads();
    if (t < 32) {
        float v = (t < 8) ? red[t] : 0.f;
#pragma unroll
        for (int o = 4; o; o >>= 1) v += __shfl_xor_sync(0xffffffffu, v, o);
        if (t == 0) red[32] = v;
    }
    __syncthreads();
    const float inv = 1.0f / red[32];
#pragma unroll
    for (int i = 0; i < 16; i++) {
        int j = t + (i << 8);
        if (j < limit) p[j] = (j < n) ? rna_tf32(vals[i] * inv) : 0.f;
    }
}

// ---------------------------------------------------------------------------
// Launch
// ---------------------------------------------------------------------------
extern "C" void kernel_launch(void* const* d_in, const int* in_sizes, int n_in,
                              void* d_out, int out_size)
{
    (void)in_sizes; (void)n_in; (void)out_size;

    const float* x  = (const float*)d_in[0];
    const float* Wq = (const float*)d_in[1];
    const float* bq = (const float*)d_in[2];
    const float* Wk = (const float*)d_in[3];
    const float* bk = (const float*)d_in[4];
    const float* Wv = (const float*)d_in[5];
    const float* bv = (const float*)d_in[6];
    const float* Wo = (const float*)d_in[7];
    const float* bo = (const float*)d_in[8];
    float* out = (float*)d_out;

    float *qp, *kp, *vp, *cp, *pp, *wt, *vt;
    cudaGetSymbolAddress((void**)&qp, g_q);
    cudaGetSymbolAddress((void**)&kp, g_k);
    cudaGetSymbolAddress((void**)&vp, g_v);
    cudaGetSymbolAddress((void**)&cp, g_ctx);
    cudaGetSymbolAddress((void**)&pp, g_p);
    cudaGetSymbolAddress((void**)&wt, g_wt);
    cudaGetSymbolAddress((void**)&vt, g_vt);

    cudaFuncSetAttribute(mma_gemm, cudaFuncAttributeMaxDynamicSharedMemorySize, SMEM_SZ);

    float* wqt = wt;
    float* wkt = wt + (size_t)DIM * DIM;
    float* wvt = wt + (size_t)2 * DIM * DIM;
    float* wot = wt + (size_t)3 * DIM * DIM;

    dim3 tb(32, 8);
    dim3 tgw(DIM / 32, DIM / 32, 1);
    transpose_k<<<tgw, tb>>>(Wq, wqt, DIM, DIM, 0, 0);
    transpose_k<<<tgw, tb>>>(Wk, wkt, DIM, DIM, 0, 0);
    transpose_k<<<tgw, tb>>>(Wv, wvt, DIM, DIM, 0, 0);
    transpose_k<<<tgw, tb>>>(Wo, wot, DIM, DIM, 0, 0);

    // round x -> cp (g_ctx doubles as rounded-x until the P@V stage)
    round_pass<<<(unsigned)((size_t)NTOK * DIM / 4 / 256), 256>>>(x, cp);

    dim3 blk(256);

    // QKV projections: [16384,1024] @ Wt^T + bias ; Q,K,ctx rounded for reuse as A
    dim3 gproj(DIM / BN, NTOK / BM, 1);
    mma_gemm<<<gproj, blk, SMEM_SZ>>>(cp, wqt, bq, qp, DIM, DIM, DIM, DIM, F_ROUND, 1.0f, 0, 0, 0);
    mma_gemm<<<gproj, blk, SMEM_SZ>>>(cp, wkt, bk, kp, DIM, DIM, DIM, DIM, F_ROUND, 1.0f, 0, 0, 0);
    mma_gemm<<<gproj, blk, SMEM_SZ>>>(cp, wvt, bv, vp, DIM, DIM, DIM, DIM, 0, 1.0f, 0, 0, 0);

    // Scores: P = (Q @ K^T) / 32, tiles not entirely above the diagonal
    dim3 gsc(SEQ / BN, SEQ / BM, BATCH);
    mma_gemm<<<gsc, blk, SMEM_SZ>>>(qp, kp, nullptr, pp, DIM, DIM, SEQ, DIM, F_TRI,
                                    1.0f / 32.0f,
                                    (size_t)SEQ * DIM, (size_t)SEQ * DIM, (size_t)SEQ * SEQ);

    // Causal softmax per row (rounds P to tf32, zero-fills to 256 boundary)
    dim3 gsm(SEQ, BATCH, 1);
    softmax_causal<<<gsm, 256>>>(pp);

    // Transpose V per batch: [SEQ, DIM] -> [DIM, SEQ], rounded
    dim3 tgv(DIM / 32, SEQ / 32, BATCH);
    transpose_k<<<tgv, tb>>>(vp, vt, SEQ, DIM, (size_t)SEQ * DIM, (size_t)DIM * SEQ);

    // ctx = P @ V (K loop causally limited); rounded since it feeds final GEMM
    dim3 gpv(DIM / BN, SEQ / BM, BATCH);
    mma_gemm<<<gpv, blk, SMEM_SZ>>>(pp, vt, nullptr, cp, SEQ, SEQ, DIM, SEQ,
                                    F_CAUSAL | F_ROUND, 1.0f,
                                    (size_t)SEQ * SEQ, (size_t)DIM * SEQ, (size_t)SEQ * DIM);

    // out = ctx @ Wo^T + bo  (no rounding on final output)
    mma_gemm<<<gproj, blk, SMEM_SZ>>>(cp, wot, bo, out, DIM, DIM, DIM, DIM, 0, 1.0f, 0, 0, 0);
}

// round 8
// speedup vs baseline: 1.0803x; 1.0803x over previous
#include <cuda_runtime.h>
#include <math.h>
#include <stdint.h>

// Problem dims (fixed by the dataset)
#define BATCH 4
#define SEQ   4096
#define DIM   1024
#define NTOK  (BATCH * SEQ)   // 16384

#define KC 32                  // K chunk per smem stage
#define PAD 36                 // row stride in floats (32 + 4 pad)
#define NSTAGE 3

// flags
#define F_CAUSAL 1   // Kend = min(Kfull, (bm+1)*128)
#define F_TRI    2   // skip tiles with bn > bm
#define F_ROUND  4   // round epilogue output to tf32 (rna)

// Scratch in device globals (no cudaMalloc allowed)
__device__ float g_q[(size_t)NTOK * DIM];
__device__ float g_k[(size_t)NTOK * DIM];
__device__ float g_v[(size_t)NTOK * DIM];
__device__ float g_ctx[(size_t)NTOK * DIM];   // holds rounded x first, then ctx
__device__ float g_p[(size_t)BATCH * SEQ * SEQ];
__device__ float g_wt[(size_t)4 * DIM * DIM];     // Wq^T, Wk^T, Wv^T, Wo^T (tf32-rounded)
__device__ float g_vt[(size_t)BATCH * DIM * SEQ]; // V^T per batch (tf32-rounded)

// ---------------------------------------------------------------------------
// helpers
// ---------------------------------------------------------------------------
__device__ __forceinline__ uint32_t smem_u32(const void* p) {
    uint32_t a;
    asm("{ .reg .u64 t; cvta.to.shared.u64 t, %1; cvt.u32.u64 %0, t; }"
        : "=r"(a) : "l"(p));
    return a;
}

__device__ __forceinline__ float rna_tf32(float x) {
    uint32_t r;
    asm("cvt.rna.tf32.f32 %0, %1;" : "=r"(r) : "f"(x));
    return __uint_as_float(r);
}

__device__ __forceinline__ void cp16(uint32_t saddr, const void* gaddr) {
    asm volatile("cp.async.cg.shared.global [%0], [%1], 16;"
                 :: "r"(saddr), "l"(gaddr));
}
#define CP_COMMIT() asm volatile("cp.async.commit_group;" ::: "memory")
#define CP_WAIT(n)  asm volatile("cp.async.wait_group %0;" :: "n"(n) : "memory")

__device__ __forceinline__ void mma_tf32(float* c, const uint32_t* a, const uint32_t* b) {
    asm volatile(
        "mma.sync.aligned.m16n8k8.row.col.f32.tf32.tf32.f32 "
        "{%0,%1,%2,%3}, {%4,%5,%6,%7}, {%8,%9}, {%0,%1,%2,%3};"
        : "+f"(c[0]), "+f"(c[1]), "+f"(c[2]), "+f"(c[3])
        : "r"(a[0]), "r"(a[1]), "r"(a[2]), "r"(a[3]), "r"(b[0]), "r"(b[1]));
}

// Smem: NSTAGE stages, each = A[128][PAD] + B[128][PAD] floats
#define A_FLOATS     (128 * PAD)                  // 4608
#define STAGE_FLOATS (2 * A_FLOATS)               // 9216
#define STAGE_BYTES  (STAGE_FLOATS * 4)           // 36864
#define A_BYTES      (A_FLOATS * 4)               // 18432
#define SMEM_SZ      (NSTAGE * STAGE_BYTES)       // 110592

// ---------------------------------------------------------------------------
// tf32 tensor-core GEMM: C[m,n] = scale * sum_k A[m,k] * Bt[n,k] (+ bias[n])
// A row-major [M x Kfull] (lda), Bt row-major [N x Kfull] (ldb; = B col-major).
// CTA 128x128, 8 warps (4x2), warp tile 32x64, mma m16n8k8.
// 3-stage cp.async pipeline, ONE __syncthreads per k-chunk.
// Operands must already be tf32-valued fp32 (pre-rounded) for full precision.
// ---------------------------------------------------------------------------
__global__ __launch_bounds__(256, 2) void mma_gemm(
    const float* __restrict__ A, const float* __restrict__ Bt,
    const float* __restrict__ bias, float* __restrict__ C,
    int lda, int ldb, int ldc, int Kfull, int flags, float scale,
    size_t sA, size_t sB, size_t sC)
{
    const int bm = blockIdx.y, bn = blockIdx.x, bz = blockIdx.z;
    if ((flags & F_TRI) && bn > bm) return;

    extern __shared__ __align__(16) float smem[];
    const uint32_t sbase = smem_u32(smem);

    const int tid  = threadIdx.x;
    const int wid  = tid >> 5, lane = tid & 31;
    const int wm   = (wid & 3) * 32;       // warp row offset in tile
    const int wn   = (wid >> 2) * 64;      // warp col offset in tile
    const int gid  = lane >> 2, tig = lane & 3;

    int Kend = Kfull;
    if (flags & F_CAUSAL) { int lim = (bm + 1) * 128; if (lim < Kend) Kend = lim; }
    const int NK = Kend / KC;

    const float* Ab = A + sA * bz + (size_t)(bm * 128) * lda;
    const float* Bb = Bt + sB * bz + (size_t)(bn * 128) * ldb;

    // per-thread gmem->smem mapping: 4 float4 per matrix per chunk
    const int lr = tid >> 3;               // 0..31 (+32 per step)
    const int lc = (tid & 7) << 2;         // 0,4,...,28

    auto issue = [&](int kc, int s) {
        const int k0 = kc * KC;
        const uint32_t base = sbase + s * STAGE_BYTES;
#pragma unroll
        for (int t = 0; t < 4; t++) {
            const int r = lr + t * 32;
            const uint32_t soff = (uint32_t)(r * PAD + lc) * 4;
            cp16(base + soff, Ab + (size_t)r * lda + k0 + lc);
            cp16(base + A_BYTES + soff, Bb + (size_t)r * ldb + k0 + lc);
        }
        CP_COMMIT();
    };

    float acc[2][8][4];
#pragma unroll
    for (int mt = 0; mt < 2; mt++)
#pragma unroll
        for (int nt = 0; nt < 8; nt++)
#pragma unroll
            for (int j = 0; j < 4; j++) acc[mt][nt][j] = 0.f;

    issue(0, 0);
    if (NK > 1) issue(1, 1);

    for (int kc = 0; kc < NK; kc++) {
        if (kc + 1 < NK) { CP_WAIT(1); } else { CP_WAIT(0); }
        __syncthreads();   // data ready + all warps done with stage (kc-1)%3
        if (kc + 2 < NK) issue(kc + 2, (kc + 2) % NSTAGE);

        const float* As = smem + (kc % NSTAGE) * STAGE_FLOATS;
        const float* Bs = As + A_FLOATS;

#pragma unroll
        for (int ks = 0; ks < 4; ks++) {
            const int kb = ks * 8 + tig;
            uint32_t a[2][4], b[8][2];
#pragma unroll
            for (int mt = 0; mt < 2; mt++) {
                const int r = wm + mt * 16 + gid;
                a[mt][0] = __float_as_uint(As[r * PAD + kb]);
                a[mt][1] = __float_as_uint(As[(r + 8) * PAD + kb]);
                a[mt][2] = __float_as_uint(As[r * PAD + kb + 4]);
                a[mt][3] = __float_as_uint(As[(r + 8) * PAD + kb + 4]);
            }
#pragma unroll
            for (int nt = 0; nt < 8; nt++) {
                const int col = wn + nt * 8 + gid;
                b[nt][0] = __float_as_uint(Bs[col * PAD + kb]);
                b[nt][1] = __float_as_uint(Bs[col * PAD + kb + 4]);
            }
#pragma unroll
            for (int mt = 0; mt < 2; mt++)
#pragma unroll
                for (int nt = 0; nt < 8; nt++)
                    mma_tf32(acc[mt][nt], a[mt], b[nt]);
        }
    }

    // Epilogue
    const int do_round = flags & F_ROUND;
    float* Cb = C + sC * bz;
#pragma unroll
    for (int mt = 0; mt < 2; mt++) {
        const int row0 = bm * 128 + wm + mt * 16 + gid;
#pragma unroll
        for (int nt = 0; nt < 8; nt++) {
            const int col = bn * 128 + wn + nt * 8 + tig * 2;
            float b0 = 0.f, b1 = 0.f;
            if (bias) { b0 = bias[col]; b1 = bias[col + 1]; }
            float2 v0, v1;
            v0.x = acc[mt][nt][0] * scale + b0;
            v0.y = acc[mt][nt][1] * scale + b1;
            v1.x = acc[mt][nt][2] * scale + b0;
            v1.y = acc[mt][nt][3] * scale + b1;
            if (do_round) {
                v0.x = rna_tf32(v0.x); v0.y = rna_tf32(v0.y);
                v1.x = rna_tf32(v1.x); v1.y = rna_tf32(v1.y);
            }
            *(float2*)(Cb + (size_t)row0 * ldc + col) = v0;
            *(float2*)(Cb + (size_t)(row0 + 8) * ldc + col) = v1;
        }
    }
}

// ---------------------------------------------------------------------------
// Tiled transpose with tf32 rounding: out[c, r] = rna(in[r, c]).
// ---------------------------------------------------------------------------
__global__ __launch_bounds__(256) void transpose_k(
    const float* __restrict__ in, float* __restrict__ out,
    int rows, int cols, size_t sIn, size_t sOut)
{
    __shared__ float tile[32][33];
    const int bx = blockIdx.x * 32, by = blockIdx.y * 32, bz = blockIdx.z;
    const float* ip = in + sIn * bz;
    float* op = out + sOut * bz;
    const int tx = threadIdx.x, ty = threadIdx.y;
#pragma unroll
    for (int i = 0; i < 4; i++)
        tile[ty + i * 8][tx] = ip[(size_t)(by + ty + i * 8) * cols + bx + tx];
    __syncthreads();
#pragma unroll
    for (int i = 0; i < 4; i++)
        op[(size_t)(bx + ty + i * 8) * rows + by + tx] = rna_tf32(tile[tx][ty + i * 8]);
}

// ---------------------------------------------------------------------------
// Elementwise tf32 rounding pass (for x).
// ---------------------------------------------------------------------------
__global__ __launch_bounds__(256) void round_pass(
    const float* __restrict__ in, float* __restrict__ out)
{
    const size_t i = ((size_t)blockIdx.x * 256 + threadIdx.x) * 4;
    float4 v = *(const float4*)(in + i);
    v.x = rna_tf32(v.x); v.y = rna_tf32(v.y);
    v.z = rna_tf32(v.z); v.w = rna_tf32(v.w);
    *(float4*)(out + i) = v;
}

// ---------------------------------------------------------------------------
// Causal row softmax; writes vals for j<n, zeros for n<=j<limit where
// limit = 128-aligned causal boundary (PV never reads beyond it). tf32-rounded.
// ---------------------------------------------------------------------------
__global__ __launch_bounds__(256) void softmax_causal(float* __restrict__ P)
{
    __shared__ float red[33];
    const int row = blockIdx.x;
    const int bz  = blockIdx.y;
    float* p = P + ((size_t)bz * SEQ + row) * SEQ;
    const int n = row + 1;
    const int limit = ((row >> 7) + 1) << 7;   // (row/128 + 1) * 128
    const int t = threadIdx.x;

    float vals[16];
    float mx = -INFINITY;
#pragma unroll
    for (int i = 0; i < 16; i++) {
        int j = t + (i << 8);
        float v = (j < n) ? p[j] : -INFINITY;
        vals[i] = v;
        mx = fmaxf(mx, v);
    }
#pragma unroll
    for (int o = 16; o; o >>= 1) mx = fmaxf(mx, __shfl_xor_sync(0xffffffffu, mx, o));
    if ((t & 31) == 0) red[t >> 5] = mx;
    __syncthreads();
    if (t < 32) {
        float v = (t < 8) ? red[t] : -INFINITY;
#pragma unroll
        for (int o = 4; o; o >>= 1) v = fmaxf(v, __shfl_xor_sync(0xffffffffu, v, o));
        if (t == 0) red[32] = v;
    }
    __syncthreads();
    mx = red[32];

    float sum = 0.f;
#pragma unroll
    for (int i = 0; i < 16; i++) {
        int j = t + (i << 8);
        float v = (j < n) ? expf(vals[i] - mx) : 0.f;
        vals[i] = v;
        sum += v;
    }
#pragma unroll
    for (int o = 16; o; o >>= 1) sum += __shfl_xor_sync(0xffffffffu, sum, o);
    __syncthreads();
    if ((t & 31) == 0) red[t >> 5] = sum;
    __syncthreads();
    if (t < 32) {
        float v = (t < 8) ? red[t] : 0.f;
#pragma unroll
        for (int o = 4; o; o >>= 1) v += __shfl_xor_sync(0xffffffffu, v, o);
        if (t == 0) red[32] = v;
    }
    __syncthreads();
    const float inv = 1.0f / red[32];
#pragma unroll
    for (int i = 0; i < 16; i++) {
        int j = t + (i << 8);
        if (j < limit) p[j] = (j < n) ? rna_tf32(vals[i] * inv) : 0.f;
    }
}

// ---------------------------------------------------------------------------
// Launch
// ---------------------------------------------------------------------------
extern "C" void kernel_launch(void* const* d_in, const int* in_sizes, int n_in,
                              void* d_out, int out_size)
{
    (void)in_sizes; (void)n_in; (void)out_size;

    const float* x  = (const float*)d_in[0];
    const float* Wq = (const float*)d_in[1];
    const float* bq = (const float*)d_in[2];
    const float* Wk = (const float*)d_in[3];
    const float* bk = (const float*)d_in[4];
    const float* Wv = (const float*)d_in[5];
    const float* bv = (const float*)d_in[6];
    const float* Wo = (const float*)d_in[7];
    const float* bo = (const float*)d_in[8];
    float* out = (float*)d_out;

    float *qp, *kp, *vp, *cp, *pp, *wt, *vt;
    cudaGetSymbolAddress((void**)&qp, g_q);
    cudaGetSymbolAddress((void**)&kp, g_k);
    cudaGetSymbolAddress((void**)&vp, g_v);
    cudaGetSymbolAddress((void**)&cp, g_ctx);
    cudaGetSymbolAddress((void**)&pp, g_p);
    cudaGetSymbolAddress((void**)&wt, g_wt);
    cudaGetSymbolAddress((void**)&vt, g_vt);

    cudaFuncSetAttribute(mma_gemm, cudaFuncAttributeMaxDynamicSharedMemorySize, SMEM_SZ);

    float* wqt = wt;
    float* wkt = wt + (size_t)DIM * DIM;
    float* wvt = wt + (size_t)2 * DIM * DIM;
    float* wot = wt + (size_t)3 * DIM * DIM;

    dim3 tb(32, 8);
    dim3 tgw(DIM / 32, DIM / 32, 1);
    transpose_k<<<tgw, tb>>>(Wq, wqt, DIM, DIM, 0, 0);
    transpose_k<<<tgw, tb>>>(Wk, wkt, DIM, DIM, 0, 0);
    transpose_k<<<tgw, tb>>>(Wv, wvt, DIM, DIM, 0, 0);
    transpose_k<<<tgw, tb>>>(Wo, wot, DIM, DIM, 0, 0);

    // round x -> cp (g_ctx doubles as rounded-x until the P@V stage)
    round_pass<<<(unsigned)((size_t)NTOK * DIM / 4 / 256), 256>>>(x, cp);

    dim3 blk(256);

    // QKV projections: [16384,1024] @ Wt^T + bias ; Q,K rounded for reuse as operands
    dim3 gproj(DIM / 128, NTOK / 128, 1);
    mma_gemm<<<gproj, blk, SMEM_SZ>>>(cp, wqt, bq, qp, DIM, DIM, DIM, DIM, F_ROUND, 1.0f, 0, 0, 0);
    mma_gemm<<<gproj, blk, SMEM_SZ>>>(cp, wkt, bk, kp, DIM, DIM, DIM, DIM, F_ROUND, 1.0f, 0, 0, 0);
    mma_gemm<<<gproj, blk, SMEM_SZ>>>(cp, wvt, bv, vp, DIM, DIM, DIM, DIM, 0, 1.0f, 0, 0, 0);

    // Scores: P = (Q @ K^T) / 32, lower-triangular tiles only
    dim3 gsc(SEQ / 128, SEQ / 128, BATCH);
    mma_gemm<<<gsc, blk, SMEM_SZ>>>(qp, kp, nullptr, pp, DIM, DIM, SEQ, DIM, F_TRI,
                                    1.0f / 32.0f,
                                    (size_t)SEQ * DIM, (size_t)SEQ * DIM, (size_t)SEQ * SEQ);

    // Causal softmax per row (rounds P to tf32, zero-fills to 128 boundary)
    dim3 gsm(SEQ, BATCH, 1);
    softmax_causal<<<gsm, 256>>>(pp);

    // Transpose V per batch: [SEQ, DIM] -> [DIM, SEQ], rounded
    dim3 tgv(DIM / 32, SEQ / 32, BATCH);
    transpose_k<<<tgv, tb>>>(vp, vt, SEQ, DIM, (size_t)SEQ * DIM, (size_t)DIM * SEQ);

    // ctx = P @ V (K loop causally limited); rounded since it feeds final GEMM
    dim3 gpv(DIM / 128, SEQ / 128, BATCH);
    mma_gemm<<<gpv, blk, SMEM_SZ>>>(pp, vt, nullptr, cp, SEQ, SEQ, DIM, SEQ,
                                    F_CAUSAL | F_ROUND, 1.0f,
                                    (size_t)SEQ * SEQ, (size_t)DIM * SEQ, (size_t)SEQ * DIM);

    // out = ctx @ Wo^T + bo  (no rounding on final output)
    mma_gemm<<<gproj, blk, SMEM_SZ>>>(cp, wot, bo, out, DIM, DIM, DIM, DIM, 0, 1.0f, 0, 0, 0);
}

// round 9
// speedup vs baseline: 1.1214x; 1.0381x over previous
#include <cuda_runtime.h>
#include <math.h>
#include <stdint.h>

// Problem dims (fixed by the dataset)
#define BATCH 4
#define SEQ   4096
#define DIM   1024
#define NTOK  (BATCH * SEQ)   // 16384

#define KC 32                  // K chunk per smem stage
#define PAD 36                 // row stride in floats (32 + 4 pad)
#define NSTAGE 3

// flags
#define F_CAUSAL 1   // Kend = min(Kfull, (bm+1)*128)
#define F_TRI    2   // skip tiles with bn > bm
#define F_ROUND  4   // round epilogue output to tf32 (rna)

// Scratch in device globals (no cudaMalloc allowed)
__device__ float g_q[(size_t)NTOK * DIM];
__device__ float g_k[(size_t)NTOK * DIM];
__device__ float g_v[(size_t)NTOK * DIM];
__device__ float g_ctx[(size_t)NTOK * DIM];   // holds rounded x first, then ctx
__device__ float g_p[(size_t)BATCH * SEQ * SEQ];
__device__ float g_wt[(size_t)4 * DIM * DIM];     // Wq^T, Wk^T, Wv^T, Wo^T (tf32-rounded)
__device__ float g_vt[(size_t)BATCH * DIM * SEQ]; // V^T per batch (tf32-rounded)

// ---------------------------------------------------------------------------
// helpers
// ---------------------------------------------------------------------------
__device__ __forceinline__ uint32_t smem_u32(const void* p) {
    uint32_t a;
    asm("{ .reg .u64 t; cvta.to.shared.u64 t, %1; cvt.u32.u64 %0, t; }"
        : "=r"(a) : "l"(p));
    return a;
}

__device__ __forceinline__ float rna_tf32(float x) {
    uint32_t r;
    asm("cvt.rna.tf32.f32 %0, %1;" : "=r"(r) : "f"(x));
    return __uint_as_float(r);
}

__device__ __forceinline__ void cp16(uint32_t saddr, const void* gaddr) {
    asm volatile("cp.async.cg.shared.global [%0], [%1], 16;"
                 :: "r"(saddr), "l"(gaddr));
}
#define CP_COMMIT() asm volatile("cp.async.commit_group;" ::: "memory")
#define CP_WAIT(n)  asm volatile("cp.async.wait_group %0;" :: "n"(n) : "memory")

__device__ __forceinline__ void mma_tf32(float* c, const uint32_t* a, const uint32_t* b) {
    asm volatile(
        "mma.sync.aligned.m16n8k8.row.col.f32.tf32.tf32.f32 "
        "{%0,%1,%2,%3}, {%4,%5,%6,%7}, {%8,%9}, {%0,%1,%2,%3};"
        : "+f"(c[0]), "+f"(c[1]), "+f"(c[2]), "+f"(c[3])
        : "r"(a[0]), "r"(a[1]), "r"(a[2]), "r"(a[3]), "r"(b[0]), "r"(b[1]));
}

// Smem: NSTAGE stages, each = A[128][PAD] + B[128][PAD] floats
#define A_FLOATS     (128 * PAD)                  // 4608
#define STAGE_FLOATS (2 * A_FLOATS)               // 9216
#define STAGE_BYTES  (STAGE_FLOATS * 4)           // 36864
#define A_BYTES      (A_FLOATS * 4)               // 18432
#define SMEM_SZ      (NSTAGE * STAGE_BYTES)       // 110592

// ---------------------------------------------------------------------------
// tf32 tensor-core GEMM: C[m,n] = scale * sum_k A[m,k] * Bt[n,k] (+ bias[n])
// A row-major [M x Kfull] (lda), Bt row-major [N x Kfull] (ldb; = B col-major).
// CTA 128x128, 4 warps (2x2), warp tile 64x64, mma m16n8k8.
// 3-stage cp.async pipeline, one __syncthreads per k-chunk.
// 64x64 warp tiles cut smem->RF crossbar bytes 3x vs 32x64 (the round-8 bind).
// Operands must already be tf32-valued fp32 (pre-rounded) for full precision.
// ---------------------------------------------------------------------------
__global__ __launch_bounds__(128, 2) void mma_gemm(
    const float* __restrict__ A, const float* __restrict__ Bt,
    const float* __restrict__ bias, float* __restrict__ C,
    int lda, int ldb, int ldc, int Kfull, int flags, float scale,
    size_t sA, size_t sB, size_t sC)
{
    const int bm = blockIdx.y, bn = blockIdx.x, bz = blockIdx.z;
    if ((flags & F_TRI) && bn > bm) return;

    extern __shared__ __align__(16) float smem[];
    const uint32_t sbase = smem_u32(smem);

    const int tid  = threadIdx.x;
    const int wid  = tid >> 5, lane = tid & 31;
    const int wm   = (wid & 1) * 64;       // warp row offset in tile
    const int wn   = (wid >> 1) * 64;      // warp col offset in tile
    const int gid  = lane >> 2, tig = lane & 3;

    int Kend = Kfull;
    if (flags & F_CAUSAL) { int lim = (bm + 1) * 128; if (lim < Kend) Kend = lim; }
    const int NK = Kend / KC;

    const float* Ab = A + sA * bz + (size_t)(bm * 128) * lda;
    const float* Bb = Bt + sB * bz + (size_t)(bn * 128) * ldb;

    // per-thread gmem->smem mapping: 8 float4 per matrix per chunk (128 thr)
    const int lr = tid >> 3;               // 0..15 (+16 per step)
    const int lc = (tid & 7) << 2;         // 0,4,...,28

    auto issue = [&](int kc, int s) {
        const int k0 = kc * KC;
        const uint32_t base = sbase + s * STAGE_BYTES;
#pragma unroll
        for (int t = 0; t < 8; t++) {
            const int r = lr + t * 16;
            const uint32_t soff = (uint32_t)(r * PAD + lc) * 4;
            cp16(base + soff, Ab + (size_t)r * lda + k0 + lc);
            cp16(base + A_BYTES + soff, Bb + (size_t)r * ldb + k0 + lc);
        }
        CP_COMMIT();
    };

    float acc[4][8][4];
#pragma unroll
    for (int mt = 0; mt < 4; mt++)
#pragma unroll
        for (int nt = 0; nt < 8; nt++)
#pragma unroll
            for (int j = 0; j < 4; j++) acc[mt][nt][j] = 0.f;

    issue(0, 0);
    if (NK > 1) issue(1, 1);

    for (int kc = 0; kc < NK; kc++) {
        if (kc + 1 < NK) { CP_WAIT(1); } else { CP_WAIT(0); }
        __syncthreads();   // data ready + all warps done with stage (kc-1)%3
        if (kc + 2 < NK) issue(kc + 2, (kc + 2) % NSTAGE);

        const float* As = smem + (kc % NSTAGE) * STAGE_FLOATS;
        const float* Bs = As + A_FLOATS;

#pragma unroll
        for (int ks = 0; ks < 4; ks++) {
            const int kb = ks * 8 + tig;
            uint32_t a[4][4], b[8][2];
#pragma unroll
            for (int mt = 0; mt < 4; mt++) {
                const int r = wm + mt * 16 + gid;
                a[mt][0] = __float_as_uint(As[r * PAD + kb]);
                a[mt][1] = __float_as_uint(As[(r + 8) * PAD + kb]);
                a[mt][2] = __float_as_uint(As[r * PAD + kb + 4]);
                a[mt][3] = __float_as_uint(As[(r + 8) * PAD + kb + 4]);
            }
#pragma unroll
            for (int nt = 0; nt < 8; nt++) {
                const int col = wn + nt * 8 + gid;
                b[nt][0] = __float_as_uint(Bs[col * PAD + kb]);
                b[nt][1] = __float_as_uint(Bs[col * PAD + kb + 4]);
            }
#pragma unroll
            for (int mt = 0; mt < 4; mt++)
#pragma unroll
                for (int nt = 0; nt < 8; nt++)
                    mma_tf32(acc[mt][nt], a[mt], b[nt]);
        }
    }

    // Epilogue
    const int do_round = flags & F_ROUND;
    float* Cb = C + sC * bz;
#pragma unroll
    for (int mt = 0; mt < 4; mt++) {
        const int row0 = bm * 128 + wm + mt * 16 + gid;
#pragma unroll
        for (int nt = 0; nt < 8; nt++) {
            const int col = bn * 128 + wn + nt * 8 + tig * 2;
            float b0 = 0.f, b1 = 0.f;
            if (bias) { b0 = bias[col]; b1 = bias[col + 1]; }
            float2 v0, v1;
            v0.x = acc[mt][nt][0] * scale + b0;
            v0.y = acc[mt][nt][1] * scale + b1;
            v1.x = acc[mt][nt][2] * scale + b0;
            v1.y = acc[mt][nt][3] * scale + b1;
            if (do_round) {
                v0.x = rna_tf32(v0.x); v0.y = rna_tf32(v0.y);
                v1.x = rna_tf32(v1.x); v1.y = rna_tf32(v1.y);
            }
            *(float2*)(Cb + (size_t)row0 * ldc + col) = v0;
            *(float2*)(Cb + (size_t)(row0 + 8) * ldc + col) = v1;
        }
    }
}

// ---------------------------------------------------------------------------
// Tiled transpose with tf32 rounding: out[c, r] = rna(in[r, c]).
// ---------------------------------------------------------------------------
__global__ __launch_bounds__(256) void transpose_k(
    const float* __restrict__ in, float* __restrict__ out,
    int rows, int cols, size_t sIn, size_t sOut)
{
    __shared__ float tile[32][33];
    const int bx = blockIdx.x * 32, by = blockIdx.y * 32, bz = blockIdx.z;
    const float* ip = in + sIn * bz;
    float* op = out + sOut * bz;
    const int tx = threadIdx.x, ty = threadIdx.y;
#pragma unroll
    for (int i = 0; i < 4; i++)
        tile[ty + i * 8][tx] = ip[(size_t)(by + ty + i * 8) * cols + bx + tx];
    __syncthreads();
#pragma unroll
    for (int i = 0; i < 4; i++)
        op[(size_t)(bx + ty + i * 8) * rows + by + tx] = rna_tf32(tile[tx][ty + i * 8]);
}

// ---------------------------------------------------------------------------
// Elementwise tf32 rounding pass (for x).
// ---------------------------------------------------------------------------
__global__ __launch_bounds__(256) void round_pass(
    const float* __restrict__ in, float* __restrict__ out)
{
    const size_t i = ((size_t)blockIdx.x * 256 + threadIdx.x) * 4;
    float4 v = *(const float4*)(in + i);
    v.x = rna_tf32(v.x); v.y = rna_tf32(v.y);
    v.z = rna_tf32(v.z); v.w = rna_tf32(v.w);
    *(float4*)(out + i) = v;
}

// ---------------------------------------------------------------------------
// Causal row softmax; writes vals for j<n, zeros for n<=j<limit where
// limit = 128-aligned causal boundary (PV never reads beyond it). tf32-rounded.
// ---------------------------------------------------------------------------
__global__ __launch_bounds__(256) void softmax_causal(float* __restrict__ P)
{
    __shared__ float red[33];
    const int row = blockIdx.x;
    const int bz  = blockIdx.y;
    float* p = P + ((size_t)bz * SEQ + row) * SEQ;
    const int n = row + 1;
    const int limit = ((row >> 7) + 1) << 7;   // (row/128 + 1) * 128
    const int t = threadIdx.x;

    float vals[16];
    float mx = -INFINITY;
#pragma unroll
    for (int i = 0; i < 16; i++) {
        int j = t + (i << 8);
        float v = (j < n) ? p[j] : -INFINITY;
        vals[i] = v;
        mx = fmaxf(mx, v);
    }
#pragma unroll
    for (int o = 16; o; o >>= 1) mx = fmaxf(mx, __shfl_xor_sync(0xffffffffu, mx, o));
    if ((t & 31) == 0) red[t >> 5] = mx;
    __syncthreads();
    if (t < 32) {
        float v = (t < 8) ? red[t] : -INFINITY;
#pragma unroll
        for (int o = 4; o; o >>= 1) v = fmaxf(v, __shfl_xor_sync(0xffffffffu, v, o));
        if (t == 0) red[32] = v;
    }
    __syncthreads();
    mx = red[32];

    float sum = 0.f;
#pragma unroll
    for (int i = 0; i < 16; i++) {
        int j = t + (i << 8);
        float v = (j < n) ? expf(vals[i] - mx) : 0.f;
        vals[i] = v;
        sum += v;
    }
#pragma unroll
    for (int o = 16; o; o >>= 1) sum += __shfl_xor_sync(0xffffffffu, sum, o);
    __syncthreads();
    if ((t & 31) == 0) red[t >> 5] = sum;
    __syncthreads();
    if (t < 32) {
        float v = (t < 8) ? red[t] : 0.f;
#pragma unroll
        for (int o = 4; o; o >>= 1) v += __shfl_xor_sync(0xffffffffu, v, o);
        if (t == 0) red[32] = v;
    }
    __syncthreads();
    const float inv = 1.0f / red[32];
#pragma unroll
    for (int i = 0; i < 16; i++) {
        int j = t + (i << 8);
        if (j < limit) p[j] = (j < n) ? rna_tf32(vals[i] * inv) : 0.f;
    }
}

// ---------------------------------------------------------------------------
// Launch
// ---------------------------------------------------------------------------
extern "C" void kernel_launch(void* const* d_in, const int* in_sizes, int n_in,
                              void* d_out, int out_size)
{
    (void)in_sizes; (void)n_in; (void)out_size;

    const float* x  = (const float*)d_in[0];
    const float* Wq = (const float*)d_in[1];
    const float* bq = (const float*)d_in[2];
    const float* Wk = (const float*)d_in[3];
    const float* bk = (const float*)d_in[4];
    const float* Wv = (const float*)d_in[5];
    const float* bv = (const float*)d_in[6];
    const float* Wo = (const float*)d_in[7];
    const float* bo = (const float*)d_in[8];
    float* out = (float*)d_out;

    float *qp, *kp, *vp, *cp, *pp, *wt, *vt;
    cudaGetSymbolAddress((void**)&qp, g_q);
    cudaGetSymbolAddress((void**)&kp, g_k);
    cudaGetSymbolAddress((void**)&vp, g_v);
    cudaGetSymbolAddress((void**)&cp, g_ctx);
    cudaGetSymbolAddress((void**)&pp, g_p);
    cudaGetSymbolAddress((void**)&wt, g_wt);
    cudaGetSymbolAddress((void**)&vt, g_vt);

    cudaFuncSetAttribute(mma_gemm, cudaFuncAttributeMaxDynamicSharedMemorySize, SMEM_SZ);

    float* wqt = wt;
    float* wkt = wt + (size_t)DIM * DIM;
    float* wvt = wt + (size_t)2 * DIM * DIM;
    float* wot = wt + (size_t)3 * DIM * DIM;

    dim3 tb(32, 8);
    dim3 tgw(DIM / 32, DIM / 32, 1);
    transpose_k<<<tgw, tb>>>(Wq, wqt, DIM, DIM, 0, 0);
    transpose_k<<<tgw, tb>>>(Wk, wkt, DIM, DIM, 0, 0);
    transpose_k<<<tgw, tb>>>(Wv, wvt, DIM, DIM, 0, 0);
    transpose_k<<<tgw, tb>>>(Wo, wot, DIM, DIM, 0, 0);

    // round x -> cp (g_ctx doubles as rounded-x until the P@V stage)
    round_pass<<<(unsigned)((size_t)NTOK * DIM / 4 / 256), 256>>>(x, cp);

    dim3 blk(128);

    // QKV projections: [16384,1024] @ Wt^T + bias ; Q,K rounded for reuse as operands
    dim3 gproj(DIM / 128, NTOK / 128, 1);
    mma_gemm<<<gproj, blk, SMEM_SZ>>>(cp, wqt, bq, qp, DIM, DIM, DIM, DIM, F_ROUND, 1.0f, 0, 0, 0);
    mma_gemm<<<gproj, blk, SMEM_SZ>>>(cp, wkt, bk, kp, DIM, DIM, DIM, DIM, F_ROUND, 1.0f, 0, 0, 0);
    mma_gemm<<<gproj, blk, SMEM_SZ>>>(cp, wvt, bv, vp, DIM, DIM, DIM, DIM, 0, 1.0f, 0, 0, 0);

    // Scores: P = (Q @ K^T) / 32, lower-triangular tiles only
    dim3 gsc(SEQ / 128, SEQ / 128, BATCH);
    mma_gemm<<<gsc, blk, SMEM_SZ>>>(qp, kp, nullptr, pp, DIM, DIM, SEQ, DIM, F_TRI,
                                    1.0f / 32.0f,
                                    (size_t)SEQ * DIM, (size_t)SEQ * DIM, (size_t)SEQ * SEQ);

    // Causal softmax per row (rounds P to tf32, zero-fills to 128 boundary)
    dim3 gsm(SEQ, BATCH, 1);
    softmax_causal<<<gsm, 256>>>(pp);

    // Transpose V per batch: [SEQ, DIM] -> [DIM, SEQ], rounded
    dim3 tgv(DIM / 32, SEQ / 32, BATCH);
    transpose_k<<<tgv, tb>>>(vp, vt, SEQ, DIM, (size_t)SEQ * DIM, (size_t)DIM * SEQ);

    // ctx = P @ V (K loop causally limited); rounded since it feeds final GEMM
    dim3 gpv(DIM / 128, SEQ / 128, BATCH);
    mma_gemm<<<gpv, blk, SMEM_SZ>>>(pp, vt, nullptr, cp, SEQ, SEQ, DIM, SEQ,
                                    F_CAUSAL | F_ROUND, 1.0f,
                                    (size_t)SEQ * SEQ, (size_t)DIM * SEQ, (size_t)SEQ * DIM);

    // out = ctx @ Wo^T + bo  (no rounding on final output)
    mma_gemm<<<gproj, blk, SMEM_SZ>>>(cp, wot, bo, out, DIM, DIM, DIM, DIM, 0, 1.0f, 0, 0, 0);
}

// round 11
// speedup vs baseline: 2.0578x; 1.8350x over previous
#include <cuda_runtime.h>
#include <cuda_fp16.h>
#include <math.h>
#include <stdint.h>

// Problem dims (fixed by the dataset)
#define BATCH 4
#define SEQ   4096
#define DIM   1024
#define NTOK  (BATCH * SEQ)   // 16384

#define KC 64                  // K halves per smem stage (128B rows)
#define PAD_H 72               // row stride in halves (64 + 8 pad)
#define NSTAGE 3

// flags
#define F_CAUSAL 1   // Kend = min(Kfull, (bm+1)*128)
#define F_TRI    2   // skip tiles with bn > bm
#define F_OUT32  4   // write fp32 output (final GEMM); else fp16

// Scratch in device globals (no cudaMalloc allowed) — all fp16 now
__device__ __half g_xh[(size_t)NTOK * DIM];
__device__ __half g_q[(size_t)NTOK * DIM];
__device__ __half g_k[(size_t)NTOK * DIM];
__device__ __half g_v[(size_t)NTOK * DIM];
__device__ __half g_ctx[(size_t)NTOK * DIM];
__device__ __half g_p[(size_t)BATCH * SEQ * SEQ];
__device__ __half g_wt[(size_t)4 * DIM * DIM];     // Wq^T, Wk^T, Wv^T, Wo^T
__device__ __half g_vt[(size_t)BATCH * DIM * SEQ]; // V^T per batch

// ---------------------------------------------------------------------------
// helpers
// ---------------------------------------------------------------------------
__device__ __forceinline__ uint32_t smem_u32(const void* p) {
    uint32_t a;
    asm("{ .reg .u64 t; cvta.to.shared.u64 t, %1; cvt.u32.u64 %0, t; }"
        : "=r"(a) : "l"(p));
    return a;
}

__device__ __forceinline__ void cp16(uint32_t saddr, const void* gaddr) {
    asm volatile("cp.async.cg.shared.global [%0], [%1], 16;"
                 :: "r"(saddr), "l"(gaddr));
}
#define CP_COMMIT() asm volatile("cp.async.commit_group;" ::: "memory")
#define CP_WAIT(n)  asm volatile("cp.async.wait_group %0;" :: "n"(n) : "memory")

// fp16 MMA, fp32 accumulate: D[16,8] += A[16,16] * B[16,8]
__device__ __forceinline__ void mma_f16(float* c, const uint32_t* a, const uint32_t* b) {
    asm volatile(
        "mma.sync.aligned.m16n8k16.row.col.f32.f16.f16.f32 "
        "{%0,%1,%2,%3}, {%4,%5,%6,%7}, {%8,%9}, {%0,%1,%2,%3};"
        : "+f"(c[0]), "+f"(c[1]), "+f"(c[2]), "+f"(c[3])
        : "r"(a[0]), "r"(a[1]), "r"(a[2]), "r"(a[3]), "r"(b[0]), "r"(b[1]));
}

// Smem: NSTAGE stages, each = A[128][PAD_H] + B[128][PAD_H] halves
#define A_HALVES     (128 * PAD_H)                // 9216 halves
#define STAGE_HALVES (2 * A_HALVES)               // 18432
#define STAGE_BYTES  (STAGE_HALVES * 2)           // 36864
#define A_BYTES      (A_HALVES * 2)               // 18432
#define SMEM_SZ      (NSTAGE * STAGE_BYTES)       // 110592

// ---------------------------------------------------------------------------
// fp16 tensor-core GEMM: C[m,n] = scale * sum_k A[m,k] * Bt[n,k] (+ bias[n])
// A row-major [M x Kfull] (lda halves), Bt row-major [N x Kfull] (ldb halves).
// CTA 128x128, 4 warps (2x2), warp tile 64x64, mma m16n8k16 (fp32 accum).
// 3-stage cp.async pipeline, one __syncthreads per k-chunk (KC=64 halves).
// fp16 operands carry the same 10-bit mantissa as the proven tf32 path.
// ---------------------------------------------------------------------------
__global__ __launch_bounds__(128, 2) void mma_gemm(
    const __half* __restrict__ A, const __half* __restrict__ Bt,
    const float* __restrict__ bias, void* __restrict__ Cv,
    int lda, int ldb, int ldc, int Kfull, int flags, float scale,
    size_t sA, size_t sB, size_t sC)
{
    const int bm = blockIdx.y, bn = blockIdx.x, bz = blockIdx.z;
    if ((flags & F_TRI) && bn > bm) return;

    extern __shared__ __align__(16) __half smem[];
    const uint32_t sbase = smem_u32(smem);

    const int tid  = threadIdx.x;
    const int wid  = tid >> 5, lane = tid & 31;
    const int wm   = (wid & 1) * 64;       // warp row offset in tile
    const int wn   = (wid >> 1) * 64;      // warp col offset in tile
    const int gid  = lane >> 2, tig = lane & 3;

    int Kend = Kfull;
    if (flags & F_CAUSAL) { int lim = (bm + 1) * 128; if (lim < Kend) Kend = lim; }
    const int NK = Kend / KC;

    const __half* Ab = A + sA * bz + (size_t)(bm * 128) * lda;
    const __half* Bb = Bt + sB * bz + (size_t)(bn * 128) * ldb;

    // gmem->smem: 8 cp16 per matrix per chunk per thread (128 thr, 16KB tiles)
    const int lr = tid >> 3;               // 0..15 (+16 per step)
    const int lc = (tid & 7) << 3;         // 0,8,...,56 halves (16B units)

    auto issue = [&](int kc, int s) {
        const int k0 = kc * KC;
        const uint32_t base = sbase + s * STAGE_BYTES;
#pragma unroll
        for (int t = 0; t < 8; t++) {
            const int r = lr + t * 16;
            const uint32_t soff = (uint32_t)(r * PAD_H + lc) * 2;
            cp16(base + soff, Ab + (size_t)r * lda + k0 + lc);
            cp16(base + A_BYTES + soff, Bb + (size_t)r * ldb + k0 + lc);
        }
        CP_COMMIT();
    };

    float acc[4][8][4];
#pragma unroll
    for (int mt = 0; mt < 4; mt++)
#pragma unroll
        for (int nt = 0; nt < 8; nt++)
#pragma unroll
            for (int j = 0; j < 4; j++) acc[mt][nt][j] = 0.f;

    issue(0, 0);
    if (NK > 1) issue(1, 1);

    for (int kc = 0; kc < NK; kc++) {
        if (kc + 1 < NK) { CP_WAIT(1); } else { CP_WAIT(0); }
        __syncthreads();   // data ready + all warps done with stage (kc-1)%3
        if (kc + 2 < NK) issue(kc + 2, (kc + 2) % NSTAGE);

        const __half* As = smem + (kc % NSTAGE) * STAGE_HALVES;
        const __half* Bs = As + A_HALVES;

#pragma unroll
        for (int ks = 0; ks < 4; ks++) {
            const int kb = ks * 16;
            uint32_t a[4][4], b[8][2];
#pragma unroll
            for (int mt = 0; mt < 4; mt++) {
                const int r = wm + mt * 16 + gid;
                a[mt][0] = *(const uint32_t*)(As + r * PAD_H + kb + tig * 2);
                a[mt][1] = *(const uint32_t*)(As + (r + 8) * PAD_H + kb + tig * 2);
                a[mt][2] = *(const uint32_t*)(As + r * PAD_H + kb + 8 + tig * 2);
                a[mt][3] = *(const uint32_t*)(As + (r + 8) * PAD_H + kb + 8 + tig * 2);
            }
#pragma unroll
            for (int nt = 0; nt < 8; nt++) {
                const int col = wn + nt * 8 + gid;
                b[nt][0] = *(const uint32_t*)(Bs + col * PAD_H + kb + tig * 2);
                b[nt][1] = *(const uint32_t*)(Bs + col * PAD_H + kb + 8 + tig * 2);
            }
#pragma unroll
            for (int mt = 0; mt < 4; mt++)
#pragma unroll
                for (int nt = 0; nt < 8; nt++)
                    mma_f16(acc[mt][nt], a[mt], b[nt]);
        }
    }

    // Epilogue
#pragma unroll
    for (int mt = 0; mt < 4; mt++) {
        const int row0 = bm * 128 + wm + mt * 16 + gid;
#pragma unroll
        for (int nt = 0; nt < 8; nt++) {
            const int col = bn * 128 + wn + nt * 8 + tig * 2;
            float b0 = 0.f, b1 = 0.f;
            if (bias) { b0 = bias[col]; b1 = bias[col + 1]; }
            float v00 = acc[mt][nt][0] * scale + b0;
            float v01 = acc[mt][nt][1] * scale + b1;
            float v10 = acc[mt][nt][2] * scale + b0;
            float v11 = acc[mt][nt][3] * scale + b1;
            if (flags & F_OUT32) {
                float* Cb = (float*)Cv + sC * bz;
                *(float2*)(Cb + (size_t)row0 * ldc + col) = make_float2(v00, v01);
                *(float2*)(Cb + (size_t)(row0 + 8) * ldc + col) = make_float2(v10, v11);
            } else {
                __half* Cb = (__half*)Cv + sC * bz;
                *(__half2*)(Cb + (size_t)row0 * ldc + col) = __floats2half2_rn(v00, v01);
                *(__half2*)(Cb + (size_t)(row0 + 8) * ldc + col) = __floats2half2_rn(v10, v11);
            }
        }
    }
}

// ---------------------------------------------------------------------------
// Tiled transpose -> fp16: out[c, r] = h(in[r, c]). Tin = float or __half.
// ---------------------------------------------------------------------------
template <typename Tin>
__global__ __launch_bounds__(256) void transpose_k(
    const Tin* __restrict__ in, __half* __restrict__ out,
    int rows, int cols, size_t sIn, size_t sOut)
{
    __shared__ float tile[32][33];
    const int bx = blockIdx.x * 32, by = blockIdx.y * 32, bz = blockIdx.z;
    const Tin* ip = in + sIn * bz;
    __half* op = out + sOut * bz;
    const int tx = threadIdx.x, ty = threadIdx.y;
#pragma unroll
    for (int i = 0; i < 4; i++)
        tile[ty + i * 8][tx] = (float)ip[(size_t)(by + ty + i * 8) * cols + bx + tx];
    __syncthreads();
#pragma unroll
    for (int i = 0; i < 4; i++)
        op[(size_t)(bx + ty + i * 8) * rows + by + tx] = __float2half_rn(tile[tx][ty + i * 8]);
}

// ---------------------------------------------------------------------------
// Elementwise fp32 -> fp16 conversion pass (for x).
// ---------------------------------------------------------------------------
__global__ __launch_bounds__(256) void round_pass(
    const float* __restrict__ in, __half* __restrict__ out)
{
    const size_t i = ((size_t)blockIdx.x * 256 + threadIdx.x) * 4;
    float4 v = *(const float4*)(in + i);
    __half2 h0 = __floats2half2_rn(v.x, v.y);
    __half2 h1 = __floats2half2_rn(v.z, v.w);
    *(__half2*)(out + i) = h0;
    *(__half2*)(out + i + 2) = h1;
}

// ---------------------------------------------------------------------------
// Causal row softmax on fp16 P; writes vals for j<n, zeros for n<=j<limit
// (128-aligned causal boundary; PV never reads beyond it).
// ---------------------------------------------------------------------------
__global__ __launch_bounds__(256) void softmax_causal(__half* __restrict__ P)
{
    __shared__ float red[33];
    const int row = blockIdx.x;
    const int bz  = blockIdx.y;
    __half* p = P + ((size_t)bz * SEQ + row) * SEQ;
    const int n = row + 1;
    const int limit = ((row >> 7) + 1) << 7;   // (row/128 + 1) * 128
    const int t = threadIdx.x;

    float vals[16];
    float mx = -INFINITY;
#pragma unroll
    for (int i = 0; i < 16; i++) {
        int j = t + (i << 8);
        float v = (j < n) ? __half2float(p[j]) : -INFINITY;
        vals[i] = v;
        mx = fmaxf(mx, v);
    }
#pragma unroll
    for (int o = 16; o; o >>= 1) mx = fmaxf(mx, __shfl_xor_sync(0xffffffffu, mx, o));
    if ((t & 31) == 0) red[t >> 5] = mx;
    __syncthreads();
    if (t < 32) {
        float v = (t < 8) ? red[t] : -INFINITY;
#pragma unroll
        for (int o = 4; o; o >>= 1) v = fmaxf(v, __shfl_xor_sync(0xffffffffu, v, o));
        if (t == 0) red[32] = v;
    }
    __syncthreads();
    mx = red[32];

    float sum = 0.f;
#pragma unroll
    for (int i = 0; i < 16; i++) {
        int j = t + (i << 8);
        float v = (j < n) ? expf(vals[i] - mx) : 0.f;
        vals[i] = v;
        sum += v;
    }
#pragma unroll
    for (int o = 16; o; o >>= 1) sum += __shfl_xor_sync(0xffffffffu, sum, o);
    __syncthreads();
    if ((t & 31) == 0) red[t >> 5] = sum;
    __syncthreads();
    if (t < 32) {
        float v = (t < 8) ? red[t] : 0.f;
#pragma unroll
        for (int o = 4; o; o >>= 1) v += __shfl_xor_sync(0xffffffffu, v, o);
        if (t == 0) red[32] = v;
    }
    __syncthreads();
    const float inv = 1.0f / red[32];
#pragma unroll
    for (int i = 0; i < 16; i++) {
        int j = t + (i << 8);
        if (j < limit) p[j] = __float2half_rn((j < n) ? vals[i] * inv : 0.f);
    }
}

// ---------------------------------------------------------------------------
// Launch
// ---------------------------------------------------------------------------
extern "C" void kernel_launch(void* const* d_in, const int* in_sizes, int n_in,
                              void* d_out, int out_size)
{
    (void)in_sizes; (void)n_in; (void)out_size;

    const float* x  = (const float*)d_in[0];
    const float* Wq = (const float*)d_in[1];
    const float* bq = (const float*)d_in[2];
    const float* Wk = (const float*)d_in[3];
    const float* bk = (const float*)d_in[4];
    const float* Wv = (const float*)d_in[5];
    const float* bv = (const float*)d_in[6];
    const float* Wo = (const float*)d_in[7];
    const float* bo = (const float*)d_in[8];
    float* out = (float*)d_out;

    __half *xh, *qp, *kp, *vp, *cp, *pp, *wt, *vt;
    cudaGetSymbolAddress((void**)&xh, g_xh);
    cudaGetSymbolAddress((void**)&qp, g_q);
    cudaGetSymbolAddress((void**)&kp, g_k);
    cudaGetSymbolAddress((void**)&vp, g_v);
    cudaGetSymbolAddress((void**)&cp, g_ctx);
    cudaGetSymbolAddress((void**)&pp, g_p);
    cudaGetSymbolAddress((void**)&wt, g_wt);
    cudaGetSymbolAddress((void**)&vt, g_vt);

    cudaFuncSetAttribute(mma_gemm, cudaFuncAttributeMaxDynamicSharedMemorySize, SMEM_SZ);

    __half* wqt = wt;
    __half* wkt = wt + (size_t)DIM * DIM;
    __half* wvt = wt + (size_t)2 * DIM * DIM;
    __half* wot = wt + (size_t)3 * DIM * DIM;

    dim3 tb(32, 8);
    dim3 tgw(DIM / 32, DIM / 32, 1);
    transpose_k<float><<<tgw, tb>>>(Wq, wqt, DIM, DIM, 0, 0);
    transpose_k<float><<<tgw, tb>>>(Wk, wkt, DIM, DIM, 0, 0);
    transpose_k<float><<<tgw, tb>>>(Wv, wvt, DIM, DIM, 0, 0);
    transpose_k<float><<<tgw, tb>>>(Wo, wot, DIM, DIM, 0, 0);

    // x -> fp16
    round_pass<<<(unsigned)((size_t)NTOK * DIM / 4 / 256), 256>>>(x, xh);

    dim3 blk(128);

    // QKV projections: [16384,1024] @ Wt^T + bias -> fp16
    dim3 gproj(DIM / 128, NTOK / 128, 1);
    mma_gemm<<<gproj, blk, SMEM_SZ>>>(xh, wqt, bq, qp, DIM, DIM, DIM, DIM, 0, 1.0f, 0, 0, 0);
    mma_gemm<<<gproj, blk, SMEM_SZ>>>(xh, wkt, bk, kp, DIM, DIM, DIM, DIM, 0, 1.0f, 0, 0, 0);
    mma_gemm<<<gproj, blk, SMEM_SZ>>>(xh, wvt, bv, vp, DIM, DIM, DIM, DIM, 0, 1.0f, 0, 0, 0);

    // Scores: P = (Q @ K^T) / 32, lower-triangular tiles only -> fp16
    dim3 gsc(SEQ / 128, SEQ / 128, BATCH);
    mma_gemm<<<gsc, blk, SMEM_SZ>>>(qp, kp, nullptr, pp, DIM, DIM, SEQ, DIM, F_TRI,
                                    1.0f / 32.0f,
                                    (size_t)SEQ * DIM, (size_t)SEQ * DIM, (size_t)SEQ * SEQ);

    // Causal softmax per row (fp16 in/out, zero-fill to 128 boundary)
    dim3 gsm(SEQ, BATCH, 1);
    softmax_causal<<<gsm, 256>>>(pp);

    // Transpose V per batch: [SEQ, DIM] -> [DIM, SEQ] fp16
    dim3 tgv(DIM / 32, SEQ / 32, BATCH);
    transpose_k<__half><<<tgv, tb>>>(vp, vt, SEQ, DIM, (size_t)SEQ * DIM, (size_t)DIM * SEQ);

    // ctx = P @ V (K loop causally limited) -> fp16
    dim3 gpv(DIM / 128, SEQ / 128, BATCH);
    mma_gemm<<<gpv, blk, SMEM_SZ>>>(pp, vt, nullptr, cp, SEQ, SEQ, DIM, SEQ, F_CAUSAL, 1.0f,
                                    (size_t)SEQ * SEQ, (size_t)DIM * SEQ, (size_t)SEQ * DIM);

    // out = ctx @ Wo^T + bo  -> fp32 harness output
    mma_gemm<<<gproj, blk, SMEM_SZ>>>(cp, wot, bo, out, DIM, DIM, DIM, DIM, F_OUT32, 1.0f, 0, 0, 0);
}

// round 13
// speedup vs baseline: 2.1892x; 1.0638x over previous
#include <cuda_runtime.h>
#include <cuda_fp16.h>
#include <math.h>
#include <stdint.h>

// Problem dims (fixed by the dataset)
#define BATCH 4
#define SEQ   4096
#define DIM   1024
#define NTOK  (BATCH * SEQ)   // 16384

#define KC 64                  // K halves per smem stage (128B rows)
#define PAD_H 72               // row stride in halves (64 + 8 pad)
#define NSTAGE 3

// flags
#define F_CAUSAL 1   // Kend = min(Kfull, (bm+1)*128)
#define F_TRIIDX 2   // derive (bm,bn) from linear blockIdx.x over lower triangle
#define F_OUT32  4   // write fp32 output (final GEMM); else fp16
#define F_REVM   8   // reverse bm order (longest-first scheduling)

// Scratch in device globals (no cudaMalloc allowed) — all fp16
__device__ __half g_xh[(size_t)NTOK * DIM];
__device__ __half g_q[(size_t)NTOK * DIM];
__device__ __half g_k[(size_t)NTOK * DIM];
__device__ __half g_v[(size_t)NTOK * DIM];
__device__ __half g_ctx[(size_t)NTOK * DIM];
__device__ __half g_p[(size_t)BATCH * SEQ * SEQ];
__device__ __half g_wt[(size_t)4 * DIM * DIM];     // Wq^T, Wk^T, Wv^T, Wo^T
__device__ __half g_vt[(size_t)BATCH * DIM * SEQ]; // V^T per batch

// ---------------------------------------------------------------------------
// helpers
// ---------------------------------------------------------------------------
__device__ __forceinline__ uint32_t smem_u32(const void* p) {
    uint32_t a;
    asm("{ .reg .u64 t; cvta.to.shared.u64 t, %1; cvt.u32.u64 %0, t; }"
        : "=r"(a) : "l"(p));
    return a;
}

__device__ __forceinline__ void cp16(uint32_t saddr, const void* gaddr) {
    asm volatile("cp.async.cg.shared.global [%0], [%1], 16;"
                 :: "r"(saddr), "l"(gaddr));
}
#define CP_COMMIT() asm volatile("cp.async.commit_group;" ::: "memory")
#define CP_WAIT(n)  asm volatile("cp.async.wait_group %0;" :: "n"(n) : "memory")

// fp16 MMA, fp32 accumulate: D[16,8] += A[16,16] * B[16,8]
__device__ __forceinline__ void mma_f16(float* c, const uint32_t* a, const uint32_t* b) {
    asm volatile(
        "mma.sync.aligned.m16n8k16.row.col.f32.f16.f16.f32 "
        "{%0,%1,%2,%3}, {%4,%5,%6,%7}, {%8,%9}, {%0,%1,%2,%3};"
        : "+f"(c[0]), "+f"(c[1]), "+f"(c[2]), "+f"(c[3])
        : "r"(a[0]), "r"(a[1]), "r"(a[2]), "r"(a[3]), "r"(b[0]), "r"(b[1]));
}

// Smem: NSTAGE stages, each = A[128][PAD_H] + B[128][PAD_H] halves
#define A_HALVES     (128 * PAD_H)                // 9216 halves
#define STAGE_HALVES (2 * A_HALVES)               // 18432
#define STAGE_BYTES  (STAGE_HALVES * 2)           // 36864
#define A_BYTES      (A_HALVES * 2)               // 18432
#define SMEM_SZ      (NSTAGE * STAGE_BYTES)       // 110592

// ---------------------------------------------------------------------------
// fp16 tensor-core GEMM: C[m,n] = scale * sum_k A[m,k] * Bt[n,k] (+ bias[n])
// A row-major [M x Kfull] (lda halves), Bt row-major [N x Kfull] (ldb halves).
// CTA 128x128, 4 warps (2x2), warp tile 64x64, mma m16n8k16 (fp32 accum).
// 3-stage cp.async pipeline, one __syncthreads per k-chunk (KC=64 halves).
// F_TRIIDX: blockIdx.x enumerates lower-triangle tiles (no null CTAs).
// F_REVM: bm reversed so costliest (causal-longest) CTAs launch first.
// ---------------------------------------------------------------------------
__global__ __launch_bounds__(128, 2) void mma_gemm(
    const __half* __restrict__ A, const __half* __restrict__ Bt,
    const float* __restrict__ bias, void* __restrict__ Cv,
    int lda, int ldb, int ldc, int Kfull, int flags, float scale,
    size_t sA, size_t sB, size_t sC)
{
    int bm, bn;
    const int bz = blockIdx.z;
    if (flags & F_TRIIDX) {
        const int bid = blockIdx.x;
        bm = (int)((sqrtf(8.0f * (float)bid + 1.0f) - 1.0f) * 0.5f);
        // guard against fp rounding
        while ((bm + 1) * (bm + 2) / 2 <= bid) bm++;
        while (bm * (bm + 1) / 2 > bid) bm--;
        bn = bid - bm * (bm + 1) / 2;
    } else {
        bm = blockIdx.y;
        bn = blockIdx.x;
        if (flags & F_REVM) bm = gridDim.y - 1 - bm;
    }

    extern __shared__ __align__(16) __half smem[];
    const uint32_t sbase = smem_u32(smem);

    const int tid  = threadIdx.x;
    const int wid  = tid >> 5, lane = tid & 31;
    const int wm   = (wid & 1) * 64;       // warp row offset in tile
    const int wn   = (wid >> 1) * 64;      // warp col offset in tile
    const int gid  = lane >> 2, tig = lane & 3;

    int Kend = Kfull;
    if (flags & F_CAUSAL) { int lim = (bm + 1) * 128; if (lim < Kend) Kend = lim; }
    const int NK = Kend / KC;

    const __half* Ab = A + sA * bz + (size_t)(bm * 128) * lda;
    const __half* Bb = Bt + sB * bz + (size_t)(bn * 128) * ldb;

    // gmem->smem: 8 cp16 per matrix per chunk per thread (128 thr, 16KB tiles)
    const int lr = tid >> 3;               // 0..15 (+16 per step)
    const int lc = (tid & 7) << 3;         // 0,8,...,56 halves (16B units)

    auto issue = [&](int kc, int s) {
        const int k0 = kc * KC;
        const uint32_t base = sbase + s * STAGE_BYTES;
#pragma unroll
        for (int t = 0; t < 8; t++) {
            const int r = lr + t * 16;
            const uint32_t soff = (uint32_t)(r * PAD_H + lc) * 2;
            cp16(base + soff, Ab + (size_t)r * lda + k0 + lc);
            cp16(base + A_BYTES + soff, Bb + (size_t)r * ldb + k0 + lc);
        }
        CP_COMMIT();
    };

    float acc[4][8][4];
#pragma unroll
    for (int mt = 0; mt < 4; mt++)
#pragma unroll
        for (int nt = 0; nt < 8; nt++)
#pragma unroll
            for (int j = 0; j < 4; j++) acc[mt][nt][j] = 0.f;

    issue(0, 0);
    if (NK > 1) issue(1, 1);

    for (int kc = 0; kc < NK; kc++) {
        if (kc + 1 < NK) { CP_WAIT(1); } else { CP_WAIT(0); }
        __syncthreads();   // data ready + all warps done with stage (kc-1)%3
        if (kc + 2 < NK) issue(kc + 2, (kc + 2) % NSTAGE);

        const __half* As = smem + (kc % NSTAGE) * STAGE_HALVES;
        const __half* Bs = As + A_HALVES;

#pragma unroll
        for (int ks = 0; ks < 4; ks++) {
            const int kb = ks * 16;
            uint32_t a[4][4], b[8][2];
#pragma unroll
            for (int mt = 0; mt < 4; mt++) {
                const int r = wm + mt * 16 + gid;
                a[mt][0] = *(const uint32_t*)(As + r * PAD_H + kb + tig * 2);
                a[mt][1] = *(const uint32_t*)(As + (r + 8) * PAD_H + kb + tig * 2);
                a[mt][2] = *(const uint32_t*)(As + r * PAD_H + kb + 8 + tig * 2);
                a[mt][3] = *(const uint32_t*)(As + (r + 8) * PAD_H + kb + 8 + tig * 2);
            }
#pragma unroll
            for (int nt = 0; nt < 8; nt++) {
                const int col = wn + nt * 8 + gid;
                b[nt][0] = *(const uint32_t*)(Bs + col * PAD_H + kb + tig * 2);
                b[nt][1] = *(const uint32_t*)(Bs + col * PAD_H + kb + 8 + tig * 2);
            }
#pragma unroll
            for (int mt = 0; mt < 4; mt++)
#pragma unroll
                for (int nt = 0; nt < 8; nt++)
                    mma_f16(acc[mt][nt], a[mt], b[nt]);
        }
    }

    // Epilogue
#pragma unroll
    for (int mt = 0; mt < 4; mt++) {
        const int row0 = bm * 128 + wm + mt * 16 + gid;
#pragma unroll
        for (int nt = 0; nt < 8; nt++) {
            const int col = bn * 128 + wn + nt * 8 + tig * 2;
            float b0 = 0.f, b1 = 0.f;
            if (bias) { b0 = bias[col]; b1 = bias[col + 1]; }
            float v00 = acc[mt][nt][0] * scale + b0;
            float v01 = acc[mt][nt][1] * scale + b1;
            float v10 = acc[mt][nt][2] * scale + b0;
            float v11 = acc[mt][nt][3] * scale + b1;
            if (flags & F_OUT32) {
                float* Cb = (float*)Cv + sC * bz;
                *(float2*)(Cb + (size_t)row0 * ldc + col) = make_float2(v00, v01);
                *(float2*)(Cb + (size_t)(row0 + 8) * ldc + col) = make_float2(v10, v11);
            } else {
                __half* Cb = (__half*)Cv + sC * bz;
                *(__half2*)(Cb + (size_t)row0 * ldc + col) = __floats2half2_rn(v00, v01);
                *(__half2*)(Cb + (size_t)(row0 + 8) * ldc + col) = __floats2half2_rn(v10, v11);
            }
        }
    }
}

// ---------------------------------------------------------------------------
// Tiled transpose -> fp16: out[c, r] = h(in[r, c]). Tin = float or __half.
// ---------------------------------------------------------------------------
template <typename Tin>
__global__ __launch_bounds__(256) void transpose_k(
    const Tin* __restrict__ in, __half* __restrict__ out,
    int rows, int cols, size_t sIn, size_t sOut)
{
    __shared__ float tile[32][33];
    const int bx = blockIdx.x * 32, by = blockIdx.y * 32, bz = blockIdx.z;
    const Tin* ip = in + sIn * bz;
    __half* op = out + sOut * bz;
    const int tx = threadIdx.x, ty = threadIdx.y;
#pragma unroll
    for (int i = 0; i < 4; i++)
        tile[ty + i * 8][tx] = (float)ip[(size_t)(by + ty + i * 8) * cols + bx + tx];
    __syncthreads();
#pragma unroll
    for (int i = 0; i < 4; i++)
        op[(size_t)(bx + ty + i * 8) * rows + by + tx] = __float2half_rn(tile[tx][ty + i * 8]);
}

// ---------------------------------------------------------------------------
// Elementwise fp32 -> fp16 conversion pass (for x).
// ---------------------------------------------------------------------------
__global__ __launch_bounds__(256) void round_pass(
    const float* __restrict__ in, __half* __restrict__ out)
{
    const size_t i = ((size_t)blockIdx.x * 256 + threadIdx.x) * 4;
    float4 v = *(const float4*)(in + i);
    *(__half2*)(out + i) = __floats2half2_rn(v.x, v.y);
    *(__half2*)(out + i + 2) = __floats2half2_rn(v.z, v.w);
}

// ---------------------------------------------------------------------------
// Causal row softmax on fp16 P, fully vectorized (uint4 = 8 halves per access).
// Writes vals for j<n, zeros for n<=j<limit (128-aligned causal boundary).
// ---------------------------------------------------------------------------
__global__ __launch_bounds__(256) void softmax_causal(__half* __restrict__ P)
{
    __shared__ float red[33];
    const int row = blockIdx.x;
    const int bz  = blockIdx.y;
    __half* p = P + ((size_t)bz * SEQ + row) * SEQ;
    const int n = row + 1;
    const int limit = ((row >> 7) + 1) << 7;   // (row/128 + 1) * 128
    const int t = threadIdx.x;

    // 2 uint4 vectors per thread: element j = (t + i*256)*8 + e
    float vals[16];
    float mx = -INFINITY;
#pragma unroll
    for (int i = 0; i < 2; i++) {
        const int vj = (t + (i << 8)) << 3;
        if (vj < n) {
            uint4 q = *(const uint4*)(p + vj);
            const __half2* h = (const __half2*)&q;
#pragma unroll
            for (int e = 0; e < 4; e++) {
                float2 f = __half22float2(h[e]);
                int j = vj + e * 2;
                float v0 = (j     < n) ? f.x : -INFINITY;
                float v1 = (j + 1 < n) ? f.y : -INFINITY;
                vals[i * 8 + e * 2]     = v0;
                vals[i * 8 + e * 2 + 1] = v1;
                mx = fmaxf(mx, fmaxf(v0, v1));
            }
        } else {
#pragma unroll
            for (int e = 0; e < 8; e++) vals[i * 8 + e] = -INFINITY;
        }
    }
#pragma unroll
    for (int o = 16; o; o >>= 1) mx = fmaxf(mx, __shfl_xor_sync(0xffffffffu, mx, o));
    if ((t & 31) == 0) red[t >> 5] = mx;
    __syncthreads();
    if (t < 32) {
        float v = (t < 8) ? red[t] : -INFINITY;
#pragma unroll
        for (int o = 4; o; o >>= 1) v = fmaxf(v, __shfl_xor_sync(0xffffffffu, v, o));
        if (t == 0) red[32] = v;
    }
    __syncthreads();
    mx = red[32];

    float sum = 0.f;
#pragma unroll
    for (int i = 0; i < 16; i++) {
        float v = (vals[i] == -INFINITY) ? 0.f : expf(vals[i] - mx);
        vals[i] = v;
        sum += v;
    }
#pragma unroll
    for (int o = 16; o; o >>= 1) sum += __shfl_xor_sync(0xffffffffu, sum, o);
    __syncthreads();
    if ((t & 31) == 0) red[t >> 5] = sum;
    __syncthreads();
    if (t < 32) {
        float v = (t < 8) ? red[t] : 0.f;
#pragma unroll
        for (int o = 4; o; o >>= 1) v += __shfl_xor_sync(0xffffffffu, v, o);
        if (t == 0) red[32] = v;
    }
    __syncthreads();
    const float inv = 1.0f / red[32];

#pragma unroll
    for (int i = 0; i < 2; i++) {
        const int vj = (t + (i << 8)) << 3;
        if (vj < limit) {   // vectors never straddle limit (both 8-aligned, limit 128-aligned)
            uint4 q;
            __half2* h = (__half2*)&q;
#pragma unroll
            for (int e = 0; e < 4; e++) {
                float v0 = vals[i * 8 + e * 2]     * inv;
                float v1 = vals[i * 8 + e * 2 + 1] * inv;
                h[e] = __floats2half2_rn(v0, v1);   // masked lanes: vals==0 -> 0
            }
            *(uint4*)(p + vj) = q;
        }
    }
}

// ---------------------------------------------------------------------------
// Launch
// ---------------------------------------------------------------------------
extern "C" void kernel_launch(void* const* d_in, const int* in_sizes, int n_in,
                              void* d_out, int out_size)
{
    (void)in_sizes; (void)n_in; (void)out_size;

    const float* x  = (const float*)d_in[0];
    const float* Wq = (const float*)d_in[1];
    const float* bq = (const float*)d_in[2];
    const float* Wk = (const float*)d_in[3];
    const float* bk = (const float*)d_in[4];
    const float* Wv = (const float*)d_in[5];
    const float* bv = (const float*)d_in[6];
    const float* Wo = (const float*)d_in[7];
    const float* bo = (const float*)d_in[8];
    float* out = (float*)d_out;

    __half *xh, *qp, *kp, *vp, *cp, *pp, *wt, *vt;
    cudaGetSymbolAddress((void**)&xh, g_xh);
    cudaGetSymbolAddress((void**)&qp, g_q);
    cudaGetSymbolAddress((void**)&kp, g_k);
    cudaGetSymbolAddress((void**)&vp, g_v);
    cudaGetSymbolAddress((void**)&cp, g_ctx);
    cudaGetSymbolAddress((void**)&pp, g_p);
    cudaGetSymbolAddress((void**)&wt, g_wt);
    cudaGetSymbolAddress((void**)&vt, g_vt);

    cudaFuncSetAttribute(mma_gemm, cudaFuncAttributeMaxDynamicSharedMemorySize, SMEM_SZ);

    __half* wqt = wt;
    __half* wkt = wt + (size_t)DIM * DIM;
    __half* wvt = wt + (size_t)2 * DIM * DIM;
    __half* wot = wt + (size_t)3 * DIM * DIM;

    dim3 tb(32, 8);
    dim3 tgw(DIM / 32, DIM / 32, 1);
    transpose_k<float><<<tgw, tb>>>(Wq, wqt, DIM, DIM, 0, 0);
    transpose_k<float><<<tgw, tb>>>(Wk, wkt, DIM, DIM, 0, 0);
    transpose_k<float><<<tgw, tb>>>(Wv, wvt, DIM, DIM, 0, 0);
    transpose_k<float><<<tgw, tb>>>(Wo, wot, DIM, DIM, 0, 0);

    // x -> fp16
    round_pass<<<(unsigned)((size_t)NTOK * DIM / 4 / 256), 256>>>(x, xh);

    dim3 blk(128);

    // QKV projections: [16384,1024] @ Wt^T + bias -> fp16
    dim3 gproj(DIM / 128, NTOK / 128, 1);
    mma_gemm<<<gproj, blk, SMEM_SZ>>>(xh, wqt, bq, qp, DIM, DIM, DIM, DIM, 0, 1.0f, 0, 0, 0);
    mma_gemm<<<gproj, blk, SMEM_SZ>>>(xh, wkt, bk, kp, DIM, DIM, DIM, DIM, 0, 1.0f, 0, 0, 0);
    mma_gemm<<<gproj, blk, SMEM_SZ>>>(xh, wvt, bv, vp, DIM, DIM, DIM, DIM, 0, 1.0f, 0, 0, 0);

    // Scores: P = (Q @ K^T) / 32 — compacted lower-triangle grid (528 tiles/batch)
    const int NTILE = SEQ / 128;                       // 32
    dim3 gsc(NTILE * (NTILE + 1) / 2, 1, BATCH);       // 528 x 1 x 4
    mma_gemm<<<gsc, blk, SMEM_SZ>>>(qp, kp, nullptr, pp, DIM, DIM, SEQ, DIM, F_TRIIDX,
                                    1.0f / 32.0f,
                                    (size_t)SEQ * DIM, (size_t)SEQ * DIM, (size_t)SEQ * SEQ);

    // Causal softmax per row (vectorized fp16, zero-fill to 128 boundary)
    dim3 gsm(SEQ, BATCH, 1);
    softmax_causal<<<gsm, 256>>>(pp);

    // Transpose V per batch: [SEQ, DIM] -> [DIM, SEQ] fp16
    dim3 tgv(DIM / 32, SEQ / 32, BATCH);
    transpose_k<__half><<<tgv, tb>>>(vp, vt, SEQ, DIM, (size_t)SEQ * DIM, (size_t)DIM * SEQ);

    // ctx = P @ V (K loop causally limited), longest row-tiles first -> fp16
    dim3 gpv(DIM / 128, SEQ / 128, BATCH);
    mma_gemm<<<gpv, blk, SMEM_SZ>>>(pp, vt, nullptr, cp, SEQ, SEQ, DIM, SEQ,
                                    F_CAUSAL | F_REVM, 1.0f,
                                    (size_t)SEQ * SEQ, (size_t)DIM * SEQ, (size_t)SEQ * DIM);

    // out = ctx @ Wo^T + bo  -> fp32 harness output
    mma_gemm<<<gproj, blk, SMEM_SZ>>>(cp, wot, bo, out, DIM, DIM, DIM, DIM, F_OUT32, 1.0f, 0, 0, 0);
}

// round 16
// speedup vs baseline: 2.2429x; 1.0246x over previous
#include <cuda_runtime.h>
#include <cuda_fp16.h>
#include <math.h>
#include <stdint.h>

// Problem dims (fixed by the dataset)
#define BATCH 4
#define SEQ   4096
#define DIM   1024
#define NTOK  (BATCH * SEQ)   // 16384

#define KC 64                  // K halves per smem stage (128B rows)
#define PAD_H 72               // row stride in halves (64 + 8 pad)
#define NSTAGE 3

// flags
#define F_CAUSAL  1   // Kend = min(Kfull, (bm+1)*128)
#define F_TRIIDX  2   // derive (bm,bn) from linear blockIdx.x over lower triangle
#define F_OUT32   4   // write fp32 output (final GEMM); else fp16
#define F_REVM    8   // reverse bm order (longest-first scheduling)
#define F_BIASROW 16  // bias indexed by output row (for transposed-V projection)

// Scratch in device globals (no cudaMalloc allowed) — all fp16
__device__ __half g_xh[(size_t)NTOK * DIM];
__device__ __half g_q[(size_t)NTOK * DIM];
__device__ __half g_k[(size_t)NTOK * DIM];
__device__ __half g_ctx[(size_t)NTOK * DIM];
__device__ __half g_p[(size_t)BATCH * SEQ * SEQ];
__device__ __half g_wt[(size_t)4 * DIM * DIM];     // Wq^T, Wk^T, Wv^T, Wo^T
__device__ __half g_vt[(size_t)BATCH * DIM * SEQ]; // V^T per batch (written directly)

// ---------------------------------------------------------------------------
// helpers
// ---------------------------------------------------------------------------
__device__ __forceinline__ uint32_t smem_u32(const void* p) {
    uint32_t a;
    asm("{ .reg .u64 t; cvta.to.shared.u64 t, %1; cvt.u32.u64 %0, t; }"
        : "=r"(a) : "l"(p));
    return a;
}

__device__ __forceinline__ void cp16(uint32_t saddr, const void* gaddr) {
    asm volatile("cp.async.cg.shared.global [%0], [%1], 16;"
                 :: "r"(saddr), "l"(gaddr));
}
#define CP_COMMIT() asm volatile("cp.async.commit_group;" ::: "memory")
#define CP_WAIT(n)  asm volatile("cp.async.wait_group %0;" :: "n"(n) : "memory")

// fp16 MMA, fp32 accumulate: D[16,8] += A[16,16] * B[16,8]
__device__ __forceinline__ void mma_f16(float* c, const uint32_t* a, const uint32_t* b) {
    asm volatile(
        "mma.sync.aligned.m16n8k16.row.col.f32.f16.f16.f32 "
        "{%0,%1,%2,%3}, {%4,%5,%6,%7}, {%8,%9}, {%0,%1,%2,%3};"
        : "+f"(c[0]), "+f"(c[1]), "+f"(c[2]), "+f"(c[3])
        : "r"(a[0]), "r"(a[1]), "r"(a[2]), "r"(a[3]), "r"(b[0]), "r"(b[1]));
}

// Smem: NSTAGE stages, each = A[128][PAD_H] + B[128][PAD_H] halves
#define A_HALVES     (128 * PAD_H)                // 9216 halves
#define STAGE_HALVES (2 * A_HALVES)               // 18432
#define STAGE_BYTES  (STAGE_HALVES * 2)           // 36864
#define A_BYTES      (A_HALVES * 2)               // 18432
#define SMEM_SZ      (NSTAGE * STAGE_BYTES)       // 110592

// ---------------------------------------------------------------------------
// fp16 tensor-core GEMM: C[m,n] = scale * sum_k A[m,k] * Bt[n,k] (+ bias)
// A row-major [M x Kfull] (lda halves), Bt row-major [N x Kfull] (ldb halves).
// CTA 128x128, 4 warps (2x2), warp tile 64x64, mma m16n8k16 (fp32 accum).
// 3-stage cp.async pipeline, one __syncthreads per k-chunk (KC=64 halves).
// F_TRIIDX: blockIdx.x enumerates lower-triangle tiles (no null CTAs).
// F_REVM: bm reversed so costliest (causal-longest) CTAs launch first.
// F_BIASROW: bias[row] instead of bias[col] (transposed-output projections).
// ---------------------------------------------------------------------------
__global__ __launch_bounds__(128, 2) void mma_gemm(
    const __half* __restrict__ A, const __half* __restrict__ Bt,
    const float* __restrict__ bias, void* __restrict__ Cv,
    int lda, int ldb, int ldc, int Kfull, int flags, float scale,
    size_t sA, size_t sB, size_t sC)
{
    int bm, bn;
    const int bz = blockIdx.z;
    if (flags & F_TRIIDX) {
        const int bid = blockIdx.x;
        bm = (int)((sqrtf(8.0f * (float)bid + 1.0f) - 1.0f) * 0.5f);
        while ((bm + 1) * (bm + 2) / 2 <= bid) bm++;
        while (bm * (bm + 1) / 2 > bid) bm--;
        bn = bid - bm * (bm + 1) / 2;
    } else {
        bm = blockIdx.y;
        bn = blockIdx.x;
        if (flags & F_REVM) bm = gridDim.y - 1 - bm;
    }

    extern __shared__ __align__(16) __half smem[];
    const uint32_t sbase = smem_u32(smem);

    const int tid  = threadIdx.x;
    const int wid  = tid >> 5, lane = tid & 31;
    const int wm   = (wid & 1) * 64;       // warp row offset in tile
    const int wn   = (wid >> 1) * 64;      // warp col offset in tile
    const int gid  = lane >> 2, tig = lane & 3;

    int Kend = Kfull;
    if (flags & F_CAUSAL) { int lim = (bm + 1) * 128; if (lim < Kend) Kend = lim; }
    const int NK = Kend / KC;

    const __half* Ab = A + sA * bz + (size_t)(bm * 128) * lda;
    const __half* Bb = Bt + sB * bz + (size_t)(bn * 128) * ldb;

    // gmem->smem: 8 cp16 per matrix per chunk per thread (128 thr, 16KB tiles)
    const int lr = tid >> 3;               // 0..15 (+16 per step)
    const int lc = (tid & 7) << 3;         // 0,8,...,56 halves (16B units)

    auto issue = [&](int kc, int s) {
        const int k0 = kc * KC;
        const uint32_t base = sbase + s * STAGE_BYTES;
#pragma unroll
        for (int t = 0; t < 8; t++) {
            const int r = lr + t * 16;
            const uint32_t soff = (uint32_t)(r * PAD_H + lc) * 2;
            cp16(base + soff, Ab + (size_t)r * lda + k0 + lc);
            cp16(base + A_BYTES + soff, Bb + (size_t)r * ldb + k0 + lc);
        }
        CP_COMMIT();
    };

    float acc[4][8][4];
#pragma unroll
    for (int mt = 0; mt < 4; mt++)
#pragma unroll
        for (int nt = 0; nt < 8; nt++)
#pragma unroll
            for (int j = 0; j < 4; j++) acc[mt][nt][j] = 0.f;

    issue(0, 0);
    if (NK > 1) issue(1, 1);

    for (int kc = 0; kc < NK; kc++) {
        if (kc + 1 < NK) { CP_WAIT(1); } else { CP_WAIT(0); }
        __syncthreads();   // data ready + all warps done with stage (kc-1)%3
        if (kc + 2 < NK) issue(kc + 2, (kc + 2) % NSTAGE);

        const __half* As = smem + (kc % NSTAGE) * STAGE_HALVES;
        const __half* Bs = As + A_HALVES;

#pragma unroll
        for (int ks = 0; ks < 4; ks++) {
            const int kb = ks * 16;
            uint32_t a[4][4], b[8][2];
#pragma unroll
            for (int mt = 0; mt < 4; mt++) {
                const int r = wm + mt * 16 + gid;
                a[mt][0] = *(const uint32_t*)(As + r * PAD_H + kb + tig * 2);
                a[mt][1] = *(const uint32_t*)(As + (r + 8) * PAD_H + kb + tig * 2);
                a[mt][2] = *(const uint32_t*)(As + r * PAD_H + kb + 8 + tig * 2);
                a[mt][3] = *(const uint32_t*)(As + (r + 8) * PAD_H + kb + 8 + tig * 2);
            }
#pragma unroll
            for (int nt = 0; nt < 8; nt++) {
                const int col = wn + nt * 8 + gid;
                b[nt][0] = *(const uint32_t*)(Bs + col * PAD_H + kb + tig * 2);
                b[nt][1] = *(const uint32_t*)(Bs + col * PAD_H + kb + 8 + tig * 2);
            }
#pragma unroll
            for (int mt = 0; mt < 4; mt++)
#pragma unroll
                for (int nt = 0; nt < 8; nt++)
                    mma_f16(acc[mt][nt], a[mt], b[nt]);
        }
    }

    // Epilogue
#pragma unroll
    for (int mt = 0; mt < 4; mt++) {
        const int row0 = bm * 128 + wm + mt * 16 + gid;
#pragma unroll
        for (int nt = 0; nt < 8; nt++) {
            const int col = bn * 128 + wn + nt * 8 + tig * 2;
            float b0 = 0.f, b1 = 0.f, br0 = 0.f, br1 = 0.f;
            if (bias) {
                if (flags & F_BIASROW) { br0 = bias[row0]; br1 = bias[row0 + 8]; }
                else { b0 = bias[col]; b1 = bias[col + 1]; }
            }
            float v00 = acc[mt][nt][0] * scale + b0 + br0;
            float v01 = acc[mt][nt][1] * scale + b1 + br0;
            float v10 = acc[mt][nt][2] * scale + b0 + br1;
            float v11 = acc[mt][nt][3] * scale + b1 + br1;
            if (flags & F_OUT32) {
                float* Cb = (float*)Cv + sC * bz;
                *(float2*)(Cb + (size_t)row0 * ldc + col) = make_float2(v00, v01);
                *(float2*)(Cb + (size_t)(row0 + 8) * ldc + col) = make_float2(v10, v11);
            } else {
                __half* Cb = (__half*)Cv + sC * bz;
                *(__half2*)(Cb + (size_t)row0 * ldc + col) = __floats2half2_rn(v00, v01);
                *(__half2*)(Cb + (size_t)(row0 + 8) * ldc + col) = __floats2half2_rn(v10, v11);
            }
        }
    }
}

// ---------------------------------------------------------------------------
// Batched weight transpose -> fp16: out_z[c, r] = h(w_z[r, c]), z = 0..3.
// ---------------------------------------------------------------------------
__global__ __launch_bounds__(256) void transpose_w4(
    const float* __restrict__ w0, const float* __restrict__ w1,
    const float* __restrict__ w2, const float* __restrict__ w3,
    __half* __restrict__ out)
{
    __shared__ float tile[32][33];
    const int bx = blockIdx.x * 32, by = blockIdx.y * 32, bz = blockIdx.z;
    const float* ip = (bz == 0) ? w0 : (bz == 1) ? w1 : (bz == 2) ? w2 : w3;
    __half* op = out + (size_t)bz * DIM * DIM;
    const int tx = threadIdx.x, ty = threadIdx.y;
#pragma unroll
    for (int i = 0; i < 4; i++)
        tile[ty + i * 8][tx] = ip[(size_t)(by + ty + i * 8) * DIM + bx + tx];
    __syncthreads();
#pragma unroll
    for (int i = 0; i < 4; i++)
        op[(size_t)(bx + ty + i * 8) * DIM + by + tx] = __float2half_rn(tile[tx][ty + i * 8]);
}

// ---------------------------------------------------------------------------
// Elementwise fp32 -> fp16 conversion pass (for x).
// ---------------------------------------------------------------------------
__global__ __launch_bounds__(256) void round_pass(
    const float* __restrict__ in, __half* __restrict__ out)
{
    const size_t i = ((size_t)blockIdx.x * 256 + threadIdx.x) * 4;
    float4 v = *(const float4*)(in + i);
    *(__half2*)(out + i) = __floats2half2_rn(v.x, v.y);
    *(__half2*)(out + i + 2) = __floats2half2_rn(v.z, v.w);
}

// ---------------------------------------------------------------------------
// Causal row softmax on fp16 P, fully vectorized (uint4 = 8 halves per access).
// Writes vals for j<n, zeros for n<=j<limit (128-aligned causal boundary).
// ---------------------------------------------------------------------------
__global__ __launch_bounds__(256) void softmax_causal(__half* __restrict__ P)
{
    __shared__ float red[33];
    const int row = blockIdx.x;
    const int bz  = blockIdx.y;
    __half* p = P + ((size_t)bz * SEQ + row) * SEQ;
    const int n = row + 1;
    const int limit = ((row >> 7) + 1) << 7;   // (row/128 + 1) * 128
    const int t = threadIdx.x;

    float vals[16];
    float mx = -INFINITY;
#pragma unroll
    for (int i = 0; i < 2; i++) {
        const int vj = (t + (i << 8)) << 3;
        if (vj < n) {
            uint4 q = *(const uint4*)(p + vj);
            const __half2* h = (const __half2*)&q;
#pragma unroll
            for (int e = 0; e < 4; e++) {
                float2 f = __half22float2(h[e]);
                int j = vj + e * 2;
                float v0 = (j     < n) ? f.x : -INFINITY;
                float v1 = (j + 1 < n) ? f.y : -INFINITY;
                vals[i * 8 + e * 2]     = v0;
                vals[i * 8 + e * 2 + 1] = v1;
                mx = fmaxf(mx, fmaxf(v0, v1));
            }
        } else {
#pragma unroll
            for (int e = 0; e < 8; e++) vals[i * 8 + e] = -INFINITY;
        }
    }
#pragma unroll
    for (int o = 16; o; o >>= 1) mx = fmaxf(mx, __shfl_xor_sync(0xffffffffu, mx, o));
    if ((t & 31) == 0) red[t >> 5] = mx;
    __syncthreads();
    if (t < 32) {
        float v = (t < 8) ? red[t] : -INFINITY;
#pragma unroll
        for (int o = 4; o; o >>= 1) v = fmaxf(v, __shfl_xor_sync(0xffffffffu, v, o));
        if (t == 0) red[32] = v;
    }
    __syncthreads();
    mx = red[32];

    float sum = 0.f;
#pragma unroll
    for (int i = 0; i < 16; i++) {
        float v = (vals[i] == -INFINITY) ? 0.f : expf(vals[i] - mx);
        vals[i] = v;
        sum += v;
    }
#pragma unroll
    for (int o = 16; o; o >>= 1) sum += __shfl_xor_sync(0xffffffffu, sum, o);
    __syncthreads();
    if ((t & 31) == 0) red[t >> 5] = sum;
    __syncthreads();
    if (t < 32) {
        float v = (t < 8) ? red[t] : 0.f;
#pragma unroll
        for (int o = 4; o; o >>= 1) v += __shfl_xor_sync(0xffffffffu, v, o);
        if (t == 0) red[32] = v;
    }
    __syncthreads();
    const float inv = 1.0f / red[32];

#pragma unroll
    for (int i = 0; i < 2; i++) {
        const int vj = (t + (i << 8)) << 3;
        if (vj < limit) {   // vectors never straddle limit (8-aligned vs 128-aligned)
            uint4 q;
            __half2* h = (__half2*)&q;
#pragma unroll
            for (int e = 0; e < 4; e++) {
                float v0 = vals[i * 8 + e * 2]     * inv;
                float v1 = vals[i * 8 + e * 2 + 1] * inv;
                h[e] = __floats2half2_rn(v0, v1);
            }
            *(uint4*)(p + vj) = q;
        }
    }
}

// ---------------------------------------------------------------------------
// Launch
// ---------------------------------------------------------------------------
extern "C" void kernel_launch(void* const* d_in, const int* in_sizes, int n_in,
                              void* d_out, int out_size)
{
    (void)in_sizes; (void)n_in; (void)out_size;

    const float* x  = (const float*)d_in[0];
    const float* Wq = (const float*)d_in[1];
    const float* bq = (const float*)d_in[2];
    const float* Wk = (const float*)d_in[3];
    const float* bk = (const float*)d_in[4];
    const float* Wv = (const float*)d_in[5];
    const float* bv = (const float*)d_in[6];
    const float* Wo = (const float*)d_in[7];
    const float* bo = (const float*)d_in[8];
    float* out = (float*)d_out;

    __half *xh, *qp, *kp, *cp, *pp, *wt, *vt;
    cudaGetSymbolAddress((void**)&xh, g_xh);
    cudaGetSymbolAddress((void**)&qp, g_q);
    cudaGetSymbolAddress((void**)&kp, g_k);
    cudaGetSymbolAddress((void**)&cp, g_ctx);
    cudaGetSymbolAddress((void**)&pp, g_p);
    cudaGetSymbolAddress((void**)&wt, g_wt);
    cudaGetSymbolAddress((void**)&vt, g_vt);

    cudaFuncSetAttribute(mma_gemm, cudaFuncAttributeMaxDynamicSharedMemorySize, SMEM_SZ);

    __half* wqt = wt;
    __half* wkt = wt + (size_t)DIM * DIM;
    __half* wvt = wt + (size_t)2 * DIM * DIM;
    __half* wot = wt + (size_t)3 * DIM * DIM;

    // All 4 weight transposes in one launch
    dim3 tb(32, 8);
    dim3 tgw(DIM / 32, DIM / 32, 4);
    transpose_w4<<<tgw, tb>>>(Wq, Wk, Wv, Wo, wt);

    // x -> fp16
    round_pass<<<(unsigned)((size_t)NTOK * DIM / 4 / 256), 256>>>(x, xh);

    dim3 blk(128);

    // Q, K projections: [16384,1024] @ Wt^T + bias -> fp16
    dim3 gproj(DIM / 128, NTOK / 128, 1);
    mma_gemm<<<gproj, blk, SMEM_SZ>>>(xh, wqt, bq, qp, DIM, DIM, DIM, DIM, 0, 1.0f, 0, 0, 0);
    mma_gemm<<<gproj, blk, SMEM_SZ>>>(xh, wkt, bk, kp, DIM, DIM, DIM, DIM, 0, 1.0f, 0, 0, 0);

    // V^T projection, written directly transposed:
    //   vt[d, s] = sum_k Wv[k, d] * x[s, k] + bv[d]
    //   A = WvT [DIM x DIM], Bt = x_batch [SEQ x DIM], bias per row (F_BIASROW)
    dim3 gvt(SEQ / 128, DIM / 128, BATCH);
    mma_gemm<<<gvt, blk, SMEM_SZ>>>(wvt, xh, bv, vt, DIM, DIM, SEQ, DIM, F_BIASROW, 1.0f,
                                    0, (size_t)SEQ * DIM, (size_t)DIM * SEQ);

    // Scores: P = (Q @ K^T) / 32 — compacted lower-triangle grid (528 tiles/batch)
    const int NTILE = SEQ / 128;                       // 32
    dim3 gsc(NTILE * (NTILE + 1) / 2, 1, BATCH);       // 528 x 1 x 4
    mma_gemm<<<gsc, blk, SMEM_SZ>>>(qp, kp, nullptr, pp, DIM, DIM, SEQ, DIM, F_TRIIDX,
                                    1.0f / 32.0f,
                                    (size_t)SEQ * DIM, (size_t)SEQ * DIM, (size_t)SEQ * SEQ);

    // Causal softmax per row (vectorized fp16, zero-fill to 128 boundary)
    dim3 gsm(SEQ, BATCH, 1);
    softmax_causal<<<gsm, 256>>>(pp);

    // ctx = P @ V (K loop causally limited), longest row-tiles first -> fp16
    dim3 gpv(DIM / 128, SEQ / 128, BATCH);
    mma_gemm<<<gpv, blk, SMEM_SZ>>>(pp, vt, nullptr, cp, SEQ, SEQ, DIM, SEQ,
                                    F_CAUSAL | F_REVM, 1.0f,
                                    (size_t)SEQ * SEQ, (size_t)DIM * SEQ, (size_t)SEQ * DIM);

    // out = ctx @ Wo^T + bo  -> fp32 harness output
    mma_gemm<<<gproj, blk, SMEM_SZ>>>(cp, wot, bo, out, DIM, DIM, DIM, DIM, F_OUT32, 1.0f, 0, 0, 0);
}

// round 17
// speedup vs baseline: 2.4887x; 1.1096x over previous
#include <cuda_runtime.h>
#include <cuda_fp16.h>
#include <math.h>
#include <stdint.h>

// Problem dims (fixed by the dataset)
#define BATCH 4
#define SEQ   4096
#define DIM   1024
#define NTOK  (BATCH * SEQ)   // 16384

#define KC 64                  // K halves per smem stage (128B rows)
#define PAD_H 72               // row stride in halves (64 + 8 pad)
#define NSTAGE 3

// flags
#define F_CAUSAL  1   // Kend = min(Kfull, (bm+1)*128)
#define F_TRIIDX  2   // derive (bm,bn) from linear blockIdx.x over lower triangle
#define F_OUT32   4   // write fp32 output (final GEMM); else fp16
#define F_REVM    8   // reverse bm order (longest-first scheduling)
#define F_BIASROW 16  // bias indexed by output row (for transposed-V projection)

// Scratch in device globals (no cudaMalloc allowed) — all fp16
__device__ __half g_xh[(size_t)NTOK * DIM];
__device__ __half g_q[(size_t)NTOK * DIM];
__device__ __half g_k[(size_t)NTOK * DIM];
__device__ __half g_ctx[(size_t)NTOK * DIM];
__device__ __half g_p[(size_t)BATCH * SEQ * SEQ];
__device__ __half g_wt[(size_t)4 * DIM * DIM];     // Wq^T, Wk^T, Wv^T, Wo^T
__device__ __half g_vt[(size_t)BATCH * DIM * SEQ]; // V^T per batch (written directly)

// ---------------------------------------------------------------------------
// helpers
// ---------------------------------------------------------------------------
__device__ __forceinline__ uint32_t smem_u32(const void* p) {
    uint32_t a;
    asm("{ .reg .u64 t; cvta.to.shared.u64 t, %1; cvt.u32.u64 %0, t; }"
        : "=r"(a) : "l"(p));
    return a;
}

__device__ __forceinline__ void cp16(uint32_t saddr, const void* gaddr) {
    asm volatile("cp.async.cg.shared.global [%0], [%1], 16;"
                 :: "r"(saddr), "l"(gaddr));
}
#define CP_COMMIT() asm volatile("cp.async.commit_group;" ::: "memory")
#define CP_WAIT(n)  asm volatile("cp.async.wait_group %0;" :: "n"(n) : "memory")

// fp16 MMA, fp32 accumulate: D[16,8] += A[16,16] * B[16,8]
__device__ __forceinline__ void mma_f16(float* c, const uint32_t* a, const uint32_t* b) {
    asm volatile(
        "mma.sync.aligned.m16n8k16.row.col.f32.f16.f16.f32 "
        "{%0,%1,%2,%3}, {%4,%5,%6,%7}, {%8,%9}, {%0,%1,%2,%3};"
        : "+f"(c[0]), "+f"(c[1]), "+f"(c[2]), "+f"(c[3])
        : "r"(a[0]), "r"(a[1]), "r"(a[2]), "r"(a[3]), "r"(b[0]), "r"(b[1]));
}

// ldmatrix x4: four 8x8 b16 tiles, lane groups of 8 supply row addresses
__device__ __forceinline__ void ldm_x4(uint32_t& r0, uint32_t& r1,
                                       uint32_t& r2, uint32_t& r3, uint32_t addr) {
    asm volatile("ldmatrix.sync.aligned.m8n8.x4.shared.b16 {%0,%1,%2,%3}, [%4];"
                 : "=r"(r0), "=r"(r1), "=r"(r2), "=r"(r3) : "r"(addr));
}

// Smem: NSTAGE stages, each = A[128][PAD_H] + B[128][PAD_H] halves
#define A_HALVES     (128 * PAD_H)                // 9216 halves
#define STAGE_HALVES (2 * A_HALVES)               // 18432
#define STAGE_BYTES  (STAGE_HALVES * 2)           // 36864
#define A_BYTES      (A_HALVES * 2)               // 18432
#define SMEM_SZ      (NSTAGE * STAGE_BYTES)       // 110592

// ---------------------------------------------------------------------------
// fp16 tensor-core GEMM: C[m,n] = scale * sum_k A[m,k] * Bt[n,k] (+ bias)
// A row-major [M x Kfull] (lda halves), Bt row-major [N x Kfull] (ldb halves).
// CTA 128x128, 4 warps (2x2), warp tile 64x64, mma m16n8k16 (fp32 accum).
// 3-stage cp.async pipeline; fragment loads via ldmatrix.x4 (4x fewer LDS).
// ---------------------------------------------------------------------------
__global__ __launch_bounds__(128, 2) void mma_gemm(
    const __half* __restrict__ A, const __half* __restrict__ Bt,
    const float* __restrict__ bias, void* __restrict__ Cv,
    int lda, int ldb, int ldc, int Kfull, int flags, float scale,
    size_t sA, size_t sB, size_t sC)
{
    int bm, bn;
    const int bz = blockIdx.z;
    if (flags & F_TRIIDX) {
        const int bid = blockIdx.x;
        bm = (int)((sqrtf(8.0f * (float)bid + 1.0f) - 1.0f) * 0.5f);
        while ((bm + 1) * (bm + 2) / 2 <= bid) bm++;
        while (bm * (bm + 1) / 2 > bid) bm--;
        bn = bid - bm * (bm + 1) / 2;
    } else {
        bm = blockIdx.y;
        bn = blockIdx.x;
        if (flags & F_REVM) bm = gridDim.y - 1 - bm;
    }

    extern __shared__ __align__(16) __half smem[];
    const uint32_t sbase = smem_u32(smem);

    const int tid  = threadIdx.x;
    const int wid  = tid >> 5, lane = tid & 31;
    const int wm   = (wid & 1) * 64;       // warp row offset in tile
    const int wn   = (wid >> 1) * 64;      // warp col offset in tile
    const int gid  = lane >> 2, tig = lane & 3;

    // ldmatrix lane->address roles
    const int a_lrow = lane & 15;          // row within 16-row A tile
    const int a_lsel = lane >> 4;          // 0: k lo half, 1: k hi half
    const int b_g    = lane & 7;           // row within 8-col B tile
    const int b_sel  = (lane >> 3) & 3;    // matrix select: (nt, khalf)

    int Kend = Kfull;
    if (flags & F_CAUSAL) { int lim = (bm + 1) * 128; if (lim < Kend) Kend = lim; }
    const int NK = Kend / KC;

    const __half* Ab = A + sA * bz + (size_t)(bm * 128) * lda;
    const __half* Bb = Bt + sB * bz + (size_t)(bn * 128) * ldb;

    // gmem->smem: 8 cp16 per matrix per chunk per thread (128 thr, 16KB tiles)
    const int lr = tid >> 3;               // 0..15 (+16 per step)
    const int lc = (tid & 7) << 3;         // 0,8,...,56 halves (16B units)

    auto issue = [&](int kc, int s) {
        const int k0 = kc * KC;
        const uint32_t base = sbase + s * STAGE_BYTES;
#pragma unroll
        for (int t = 0; t < 8; t++) {
            const int r = lr + t * 16;
            const uint32_t soff = (uint32_t)(r * PAD_H + lc) * 2;
            cp16(base + soff, Ab + (size_t)r * lda + k0 + lc);
            cp16(base + A_BYTES + soff, Bb + (size_t)r * ldb + k0 + lc);
        }
        CP_COMMIT();
    };

    float acc[4][8][4];
#pragma unroll
    for (int mt = 0; mt < 4; mt++)
#pragma unroll
        for (int nt = 0; nt < 8; nt++)
#pragma unroll
            for (int j = 0; j < 4; j++) acc[mt][nt][j] = 0.f;

    issue(0, 0);
    if (NK > 1) issue(1, 1);

    for (int kc = 0; kc < NK; kc++) {
        if (kc + 1 < NK) { CP_WAIT(1); } else { CP_WAIT(0); }
        __syncthreads();   // data ready + all warps done with stage (kc-1)%3
        if (kc + 2 < NK) issue(kc + 2, (kc + 2) % NSTAGE);

        const uint32_t As_u = sbase + (kc % NSTAGE) * STAGE_BYTES;
        const uint32_t Bs_u = As_u + A_BYTES;

#pragma unroll
        for (int ks = 0; ks < 4; ks++) {
            const int kb = ks * 16;
            uint32_t a[4][4], b[8][2];
            // A fragments: one ldmatrix.x4 per 16-row tile
            //   m0: rows[0-7]@kb, m1: rows[8-15]@kb, m2: rows[0-7]@kb+8, m3: rows[8-15]@kb+8
#pragma unroll
            for (int mt = 0; mt < 4; mt++) {
                const uint32_t addr = As_u +
                    (uint32_t)((wm + mt * 16 + a_lrow) * PAD_H + kb + a_lsel * 8) * 2;
                ldm_x4(a[mt][0], a[mt][1], a[mt][2], a[mt][3], addr);
            }
            // B fragments: one ldmatrix.x4 per nt-pair
            //   m0: ntA@kb, m1: ntA@kb+8, m2: ntB@kb, m3: ntB@kb+8
#pragma unroll
            for (int np = 0; np < 4; np++) {
                const int ntx = 2 * np + (b_sel >> 1);
                const uint32_t addr = Bs_u +
                    (uint32_t)((wn + ntx * 8 + b_g) * PAD_H + kb + (b_sel & 1) * 8) * 2;
                ldm_x4(b[2 * np][0], b[2 * np][1], b[2 * np + 1][0], b[2 * np + 1][1], addr);
            }
#pragma unroll
            for (int mt = 0; mt < 4; mt++)
#pragma unroll
                for (int nt = 0; nt < 8; nt++)
                    mma_f16(acc[mt][nt], a[mt], b[nt]);
        }
    }

    // Epilogue
#pragma unroll
    for (int mt = 0; mt < 4; mt++) {
        const int row0 = bm * 128 + wm + mt * 16 + gid;
#pragma unroll
        for (int nt = 0; nt < 8; nt++) {
            const int col = bn * 128 + wn + nt * 8 + tig * 2;
            float b0 = 0.f, b1 = 0.f, br0 = 0.f, br1 = 0.f;
            if (bias) {
                if (flags & F_BIASROW) { br0 = bias[row0]; br1 = bias[row0 + 8]; }
                else { b0 = bias[col]; b1 = bias[col + 1]; }
            }
            float v00 = acc[mt][nt][0] * scale + b0 + br0;
            float v01 = acc[mt][nt][1] * scale + b1 + br0;
            float v10 = acc[mt][nt][2] * scale + b0 + br1;
            float v11 = acc[mt][nt][3] * scale + b1 + br1;
            if (flags & F_OUT32) {
                float* Cb = (float*)Cv + sC * bz;
                *(float2*)(Cb + (size_t)row0 * ldc + col) = make_float2(v00, v01);
                *(float2*)(Cb + (size_t)(row0 + 8) * ldc + col) = make_float2(v10, v11);
            } else {
                __half* Cb = (__half*)Cv + sC * bz;
                *(__half2*)(Cb + (size_t)row0 * ldc + col) = __floats2half2_rn(v00, v01);
                *(__half2*)(Cb + (size_t)(row0 + 8) * ldc + col) = __floats2half2_rn(v10, v11);
            }
        }
    }
}

// ---------------------------------------------------------------------------
// Batched weight transpose -> fp16: out_z[c, r] = h(w_z[r, c]), z = 0..3.
// ---------------------------------------------------------------------------
__global__ __launch_bounds__(256) void transpose_w4(
    const float* __restrict__ w0, const float* __restrict__ w1,
    const float* __restrict__ w2, const float* __restrict__ w3,
    __half* __restrict__ out)
{
    __shared__ float tile[32][33];
    const int bx = blockIdx.x * 32, by = blockIdx.y * 32, bz = blockIdx.z;
    const float* ip = (bz == 0) ? w0 : (bz == 1) ? w1 : (bz == 2) ? w2 : w3;
    __half* op = out + (size_t)bz * DIM * DIM;
    const int tx = threadIdx.x, ty = threadIdx.y;
#pragma unroll
    for (int i = 0; i < 4; i++)
        tile[ty + i * 8][tx] = ip[(size_t)(by + ty + i * 8) * DIM + bx + tx];
    __syncthreads();
#pragma unroll
    for (int i = 0; i < 4; i++)
        op[(size_t)(bx + ty + i * 8) * DIM + by + tx] = __float2half_rn(tile[tx][ty + i * 8]);
}

// ---------------------------------------------------------------------------
// Elementwise fp32 -> fp16 conversion pass (for x).
// ---------------------------------------------------------------------------
__global__ __launch_bounds__(256) void round_pass(
    const float* __restrict__ in, __half* __restrict__ out)
{
    const size_t i = ((size_t)blockIdx.x * 256 + threadIdx.x) * 4;
    float4 v = *(const float4*)(in + i);
    *(__half2*)(out + i) = __floats2half2_rn(v.x, v.y);
    *(__half2*)(out + i + 2) = __floats2half2_rn(v.z, v.w);
}

// ---------------------------------------------------------------------------
// Causal row softmax on fp16 P, fully vectorized (uint4 = 8 halves per access).
// Writes vals for j<n, zeros for n<=j<limit (128-aligned causal boundary).
// ---------------------------------------------------------------------------
__global__ __launch_bounds__(256) void softmax_causal(__half* __restrict__ P)
{
    __shared__ float red[33];
    const int row = blockIdx.x;
    const int bz  = blockIdx.y;
    __half* p = P + ((size_t)bz * SEQ + row) * SEQ;
    const int n = row + 1;
    const int limit = ((row >> 7) + 1) << 7;   // (row/128 + 1) * 128
    const int t = threadIdx.x;

    float vals[16];
    float mx = -INFINITY;
#pragma unroll
    for (int i = 0; i < 2; i++) {
        const int vj = (t + (i << 8)) << 3;
        if (vj < n) {
            uint4 q = *(const uint4*)(p + vj);
            const __half2* h = (const __half2*)&q;
#pragma unroll
            for (int e = 0; e < 4; e++) {
                float2 f = __half22float2(h[e]);
                int j = vj + e * 2;
                float v0 = (j     < n) ? f.x : -INFINITY;
                float v1 = (j + 1 < n) ? f.y : -INFINITY;
                vals[i * 8 + e * 2]     = v0;
                vals[i * 8 + e * 2 + 1] = v1;
                mx = fmaxf(mx, fmaxf(v0, v1));
            }
        } else {
#pragma unroll
            for (int e = 0; e < 8; e++) vals[i * 8 + e] = -INFINITY;
        }
    }
#pragma unroll
    for (int o = 16; o; o >>= 1) mx = fmaxf(mx, __shfl_xor_sync(0xffffffffu, mx, o));
    if ((t & 31) == 0) red[t >> 5] = mx;
    __syncthreads();
    if (t < 32) {
        float v = (t < 8) ? red[t] : -INFINITY;
#pragma unroll
        for (int o = 4; o; o >>= 1) v = fmaxf(v, __shfl_xor_sync(0xffffffffu, v, o));
        if (t == 0) red[32] = v;
    }
    __syncthreads();
    mx = red[32];

    float sum = 0.f;
#pragma unroll
    for (int i = 0; i < 16; i++) {
        float v = (vals[i] == -INFINITY) ? 0.f : expf(vals[i] - mx);
        vals[i] = v;
        sum += v;
    }
#pragma unroll
    for (int o = 16; o; o >>= 1) sum += __shfl_xor_sync(0xffffffffu, sum, o);
    __syncthreads();
    if ((t & 31) == 0) red[t >> 5] = sum;
    __syncthreads();
    if (t < 32) {
        float v = (t < 8) ? red[t] : 0.f;
#pragma unroll
        for (int o = 4; o; o >>= 1) v += __shfl_xor_sync(0xffffffffu, v, o);
        if (t == 0) red[32] = v;
    }
    __syncthreads();
    const float inv = 1.0f / red[32];

#pragma unroll
    for (int i = 0; i < 2; i++) {
        const int vj = (t + (i << 8)) << 3;
        if (vj < limit) {   // vectors never straddle limit (8-aligned vs 128-aligned)
            uint4 q;
            __half2* h = (__half2*)&q;
#pragma unroll
            for (int e = 0; e < 4; e++) {
                float v0 = vals[i * 8 + e * 2]     * inv;
                float v1 = vals[i * 8 + e * 2 + 1] * inv;
                h[e] = __floats2half2_rn(v0, v1);
            }
            *(uint4*)(p + vj) = q;
        }
    }
}

// ---------------------------------------------------------------------------
// Launch
// ---------------------------------------------------------------------------
extern "C" void kernel_launch(void* const* d_in, const int* in_sizes, int n_in,
                              void* d_out, int out_size)
{
    (void)in_sizes; (void)n_in; (void)out_size;

    const float* x  = (const float*)d_in[0];
    const float* Wq = (const float*)d_in[1];
    const float* bq = (const float*)d_in[2];
    const float* Wk = (const float*)d_in[3];
    const float* bk = (const float*)d_in[4];
    const float* Wv = (const float*)d_in[5];
    const float* bv = (const float*)d_in[6];
    const float* Wo = (const float*)d_in[7];
    const float* bo = (const float*)d_in[8];
    float* out = (float*)d_out;

    __half *xh, *qp, *kp, *cp, *pp, *wt, *vt;
    cudaGetSymbolAddress((void**)&xh, g_xh);
    cudaGetSymbolAddress((void**)&qp, g_q);
    cudaGetSymbolAddress((void**)&kp, g_k);
    cudaGetSymbolAddress((void**)&cp, g_ctx);
    cudaGetSymbolAddress((void**)&pp, g_p);
    cudaGetSymbolAddress((void**)&wt, g_wt);
    cudaGetSymbolAddress((void**)&vt, g_vt);

    cudaFuncSetAttribute(mma_gemm, cudaFuncAttributeMaxDynamicSharedMemorySize, SMEM_SZ);

    __half* wqt = wt;
    __half* wkt = wt + (size_t)DIM * DIM;
    __half* wvt = wt + (size_t)2 * DIM * DIM;
    __half* wot = wt + (size_t)3 * DIM * DIM;

    // All 4 weight transposes in one launch
    dim3 tb(32, 8);
    dim3 tgw(DIM / 32, DIM / 32, 4);
    transpose_w4<<<tgw, tb>>>(Wq, Wk, Wv, Wo, wt);

    // x -> fp16
    round_pass<<<(unsigned)((size_t)NTOK * DIM / 4 / 256), 256>>>(x, xh);

    dim3 blk(128);

    // Q, K projections: [16384,1024] @ Wt^T + bias -> fp16
    dim3 gproj(DIM / 128, NTOK / 128, 1);
    mma_gemm<<<gproj, blk, SMEM_SZ>>>(xh, wqt, bq, qp, DIM, DIM, DIM, DIM, 0, 1.0f, 0, 0, 0);
    mma_gemm<<<gproj, blk, SMEM_SZ>>>(xh, wkt, bk, kp, DIM, DIM, DIM, DIM, 0, 1.0f, 0, 0, 0);

    // V^T projection, written directly transposed:
    //   vt[d, s] = sum_k Wv[k, d] * x[s, k] + bv[d]
    dim3 gvt(SEQ / 128, DIM / 128, BATCH);
    mma_gemm<<<gvt, blk, SMEM_SZ>>>(wvt, xh, bv, vt, DIM, DIM, SEQ, DIM, F_BIASROW, 1.0f,
                                    0, (size_t)SEQ * DIM, (size_t)DIM * SEQ);

    // Scores: P = (Q @ K^T) / 32 — compacted lower-triangle grid (528 tiles/batch)
    const int NTILE = SEQ / 128;                       // 32
    dim3 gsc(NTILE * (NTILE + 1) / 2, 1, BATCH);       // 528 x 1 x 4
    mma_gemm<<<gsc, blk, SMEM_SZ>>>(qp, kp, nullptr, pp, DIM, DIM, SEQ, DIM, F_TRIIDX,
                                    1.0f / 32.0f,
                                    (size_t)SEQ * DIM, (size_t)SEQ * DIM, (size_t)SEQ * SEQ);

    // Causal softmax per row (vectorized fp16, zero-fill to 128 boundary)
    dim3 gsm(SEQ, BATCH, 1);
    softmax_causal<<<gsm, 256>>>(pp);

    // ctx = P @ V (K loop causally limited), longest row-tiles first -> fp16
    dim3 gpv(DIM / 128, SEQ / 128, BATCH);
    mma_gemm<<<gpv, blk, SMEM_SZ>>>(pp, vt, nullptr, cp, SEQ, SEQ, DIM, SEQ,
                                    F_CAUSAL | F_REVM, 1.0f,
                                    (size_t)SEQ * SEQ, (size_t)DIM * SEQ, (size_t)SEQ * DIM);

    // out = ctx @ Wo^T + bo  -> fp32 harness output
    mma_gemm<<<gproj, blk, SMEM_SZ>>>(cp, wot, bo, out, DIM, DIM, DIM, DIM, F_OUT32, 1.0f, 0, 0, 0);
}